// round 2
// baseline (speedup 1.0000x reference)
#include <cuda_runtime.h>
#include <math.h>

#define NMAX 100000
#define EMAX 1600000
#define F 128

// ---------------- scratch (device globals: no allocation allowed) ----------
__device__ float g_deg[NMAX];                    // degree, then 1/max(deg,1)
__device__ float g_agg[(size_t)NMAX * F];        // neighbor sum / scaled mean
__device__ float g_h1[(size_t)NMAX * F];
__device__ float g_h2[(size_t)NMAX * F];
__device__ unsigned int g_mm[2];                 // [0]=encoded min, [1]=encoded max

// order-preserving float -> uint encoding (for atomicMin/Max on floats)
__device__ __forceinline__ unsigned fenc(float f) {
    unsigned u = __float_as_uint(f);
    return (u & 0x80000000u) ? ~u : (u | 0x80000000u);
}
__device__ __forceinline__ float fdec(unsigned u) {
    return __uint_as_float((u & 0x80000000u) ? (u ^ 0x80000000u) : ~u);
}

// ---------------- degree -----------------------------------------------------
__global__ void k_deg(const int* __restrict__ dst, int e) {
    int i = blockIdx.x * blockDim.x + threadIdx.x;
    if (i < e) atomicAdd(&g_deg[dst[i]], 1.0f);
}

__global__ void k_invdeg(int n) {
    int i = blockIdx.x * blockDim.x + threadIdx.x;
    if (i < n) g_deg[i] = 1.0f / fmaxf(g_deg[i], 1.0f);
}

// ---------------- scatter aggregation: warp per edge, red.v4 ----------------
__global__ void k_agg(const float* __restrict__ h, const int* __restrict__ src,
                      const int* __restrict__ dst, int e) {
    int w = (blockIdx.x * blockDim.x + threadIdx.x) >> 5;
    if (w >= e) return;
    int lane = threadIdx.x & 31;
    int s = __ldg(src + w);
    int d = __ldg(dst + w);
    float4 v = __ldg(((const float4*)h) + (size_t)s * 32 + lane);
    float* p = g_agg + (size_t)d * F + lane * 4;
    asm volatile("red.global.add.v4.f32 [%0], {%1, %2, %3, %4};"
                 :: "l"(p), "f"(v.x), "f"(v.y), "f"(v.z), "f"(v.w) : "memory");
}

// ---------------- agg *= inv_deg (turn sum into mean) ------------------------
__global__ void k_scale(int n) {
    int i = blockIdx.x * blockDim.x + threadIdx.x;  // over n*32 float4
    if (i >= n * 32) return;
    float inv = g_deg[i >> 5];
    float4* p = ((float4*)g_agg) + i;
    float4 v = *p;
    v.x *= inv; v.y *= inv; v.z *= inv; v.w *= inv;
    *p = v;
}

// ---------------- fused SAGE GEMM: out = A1@W1 + A2@W2 + bias ---------------
// Treated as [N,256] @ [256,128]. W (both matrices) + transposed 64-row A tile
// staged in SMEM. Block: 256 threads, 64 rows x 128 cols, 2x16 outputs/thread.
__global__ void __launch_bounds__(256, 1)
k_gemm(const float* __restrict__ A1, const float* __restrict__ A2,
       const float* __restrict__ W1, const float* __restrict__ W2,
       const float* __restrict__ bias, float* __restrict__ out, int n) {
    extern __shared__ float sm[];
    float* Ws = sm;               // [256][128]            = 128 KB
    float* As = sm + 256 * 128;   // [256][65] (k-major)   = 65 KB (padded)

    const int tid = threadIdx.x;
    const int tx = tid & 7;       // 8 column groups
    const int ty = tid >> 3;      // 32 row slots (rows ty and ty+32)
    const int base = blockIdx.x * 64;

    // stage W: rows 0..127 = W1, rows 128..255 = W2 (row-major, coalesced)
    {
        const float4* w1 = (const float4*)W1;
        const float4* w2 = (const float4*)W2;
        float4* ws4 = (float4*)Ws;
        for (int i = tid; i < 8192; i += 256)
            ws4[i] = (i < 4096) ? __ldg(w1 + i) : __ldg(w2 + (i - 4096));
    }

    // stage A transposed: As[k][r], k in [0,256), r in [0,64)
    for (int i = tid; i < 64 * 64; i += 256) {
        int r  = i >> 6;
        int c4 = i & 63;          // float4 column within the 256-wide row
        int row = base + r;
        float4 v = make_float4(0.f, 0.f, 0.f, 0.f);
        if (row < n)
            v = (c4 < 32) ? __ldg((const float4*)A1 + (size_t)row * 32 + c4)
                          : __ldg((const float4*)A2 + (size_t)row * 32 + (c4 - 32));
        int k0 = c4 * 4;
        As[(k0 + 0) * 65 + r] = v.x;
        As[(k0 + 1) * 65 + r] = v.y;
        As[(k0 + 2) * 65 + r] = v.z;
        As[(k0 + 3) * 65 + r] = v.w;
    }
    __syncthreads();

    float acc0[16], acc1[16];
#pragma unroll
    for (int j = 0; j < 16; j++) { acc0[j] = 0.f; acc1[j] = 0.f; }

#pragma unroll 4
    for (int k = 0; k < 256; ++k) {
        float a0 = As[k * 65 + ty];
        float a1 = As[k * 65 + 32 + ty];
        const float4* wr = (const float4*)(Ws + k * 128);
#pragma unroll
        for (int j = 0; j < 4; ++j) {
            float4 w = wr[tx + 8 * j];   // col group tx*4 + 32*j : conflict-free
            acc0[j * 4 + 0] += a0 * w.x; acc0[j * 4 + 1] += a0 * w.y;
            acc0[j * 4 + 2] += a0 * w.z; acc0[j * 4 + 3] += a0 * w.w;
            acc1[j * 4 + 0] += a1 * w.x; acc1[j * 4 + 1] += a1 * w.y;
            acc1[j * 4 + 2] += a1 * w.z; acc1[j * 4 + 3] += a1 * w.w;
        }
    }

    int row0 = base + ty;
    int row1 = base + 32 + ty;
#pragma unroll
    for (int j = 0; j < 4; ++j) {
        int c4 = tx + 8 * j;
        float4 bv = __ldg((const float4*)bias + c4);
        if (row0 < n) {
            float4 o;
            o.x = acc0[j * 4 + 0] + bv.x; o.y = acc0[j * 4 + 1] + bv.y;
            o.z = acc0[j * 4 + 2] + bv.z; o.w = acc0[j * 4 + 3] + bv.w;
            ((float4*)out)[(size_t)row0 * 32 + c4] = o;
        }
        if (row1 < n) {
            float4 o;
            o.x = acc1[j * 4 + 0] + bv.x; o.y = acc1[j * 4 + 1] + bv.y;
            o.z = acc1[j * 4 + 2] + bv.z; o.w = acc1[j * 4 + 3] + bv.w;
            ((float4*)out)[(size_t)row1 * 32 + c4] = o;
        }
    }
}

// ---------------- edge scores: warp per edge (grid-stride) + min/max --------
__global__ void k_score(const float* __restrict__ h, const int* __restrict__ src,
                        const int* __restrict__ dst, float* __restrict__ out, int e) {
    int gw = (blockIdx.x * blockDim.x + threadIdx.x) >> 5;
    int nw = (gridDim.x * blockDim.x) >> 5;
    int lane = threadIdx.x & 31;
    float lmin = 3.402823466e38f;
    float lmax = -3.402823466e38f;

    for (int i = gw; i < e; i += nw) {
        int s = __ldg(src + i);
        int d = __ldg(dst + i);
        float4 a = __ldg((const float4*)h + (size_t)s * 32 + lane);
        float4 b = __ldg((const float4*)h + (size_t)d * 32 + lane);
        float p = a.x * b.x + a.y * b.y + a.z * b.z + a.w * b.w;
#pragma unroll
        for (int o = 16; o; o >>= 1) p += __shfl_xor_sync(0xffffffffu, p, o);
        if (lane == 0) {
            out[i] = p;
            lmin = fminf(lmin, p);
            lmax = fmaxf(lmax, p);
        }
    }

    // block-level min/max reduction, then 2 global atomics per block
#pragma unroll
    for (int o = 16; o; o >>= 1) {
        lmin = fminf(lmin, __shfl_xor_sync(0xffffffffu, lmin, o));
        lmax = fmaxf(lmax, __shfl_xor_sync(0xffffffffu, lmax, o));
    }
    __shared__ float smin[8], smax[8];
    int wid = threadIdx.x >> 5;
    if (lane == 0) { smin[wid] = lmin; smax[wid] = lmax; }
    __syncthreads();
    if (threadIdx.x == 0) {
        float m0 = smin[0], m1 = smax[0];
#pragma unroll
        for (int i = 1; i < 8; i++) { m0 = fminf(m0, smin[i]); m1 = fmaxf(m1, smax[i]); }
        atomicMin(&g_mm[0], fenc(m0));
        atomicMax(&g_mm[1], fenc(m1));
    }
}

__global__ void k_norm(float* __restrict__ out, int e) {
    int i = blockIdx.x * blockDim.x + threadIdx.x;
    if (i >= e) return;
    float mn = fdec(g_mm[0]);
    float mx = fdec(g_mm[1]);
    float inv = 1.0f / (mx - mn);
    out[i] = (out[i] - mn) * inv;
}

// ---------------- launch ------------------------------------------------------
extern "C" void kernel_launch(void* const* d_in, const int* in_sizes, int n_in,
                              void* d_out, int out_size) {
    const float* x   = (const float*)d_in[0];
    const int*   src = (const int*)d_in[1];
    const int*   dst = (const int*)d_in[2];
    const float* Ws1 = (const float*)d_in[3];
    const float* Wn1 = (const float*)d_in[4];
    const float* b1  = (const float*)d_in[5];
    const float* Ws2 = (const float*)d_in[6];
    const float* Wn2 = (const float*)d_in[7];
    const float* b2  = (const float*)d_in[8];
    float* out = (float*)d_out;

    int n = in_sizes[0] / F;
    int e = in_sizes[1];

    void *p_deg, *p_agg, *p_h1, *p_h2, *p_mm;
    cudaGetSymbolAddress(&p_deg, g_deg);
    cudaGetSymbolAddress(&p_agg, g_agg);
    cudaGetSymbolAddress(&p_h1, g_h1);
    cudaGetSymbolAddress(&p_h2, g_h2);
    cudaGetSymbolAddress(&p_mm, g_mm);

    const int tpb = 256;
    const size_t SMEM = (256 * 128 + 256 * 65) * sizeof(float);  // 197,632 B
    cudaFuncSetAttribute(k_gemm, cudaFuncAttributeMaxDynamicSharedMemorySize, (int)SMEM);

    // init scratch
    cudaMemsetAsync(p_deg, 0, (size_t)n * sizeof(float), 0);
    cudaMemsetAsync(p_agg, 0, (size_t)n * F * sizeof(float), 0);
    cudaMemsetAsync(p_mm, 0xFF, 4, 0);                  // encoded min init
    cudaMemsetAsync((char*)p_mm + 4, 0x00, 4, 0);       // encoded max init

    // degrees (shared by both layers)
    k_deg<<<(e + tpb - 1) / tpb, tpb>>>(dst, e);
    k_invdeg<<<(n + tpb - 1) / tpb, tpb>>>(n);

    long aggThreads = (long)e * 32;
    int aggBlocks = (int)((aggThreads + tpb - 1) / tpb);
    int gemmBlocks = (n + 63) / 64;
    int scaleBlocks = (n * 32 + tpb - 1) / tpb;

    // layer 1
    k_agg<<<aggBlocks, tpb>>>(x, src, dst, e);
    k_scale<<<scaleBlocks, tpb>>>(n);
    k_gemm<<<gemmBlocks, 256, SMEM>>>(x, (const float*)p_agg, Ws1, Wn1, b1,
                                      (float*)p_h1, n);

    // layer 2
    cudaMemsetAsync(p_agg, 0, (size_t)n * F * sizeof(float), 0);
    k_agg<<<aggBlocks, tpb>>>((const float*)p_h1, src, dst, e);
    k_scale<<<scaleBlocks, tpb>>>(n);
    k_gemm<<<gemmBlocks, 256, SMEM>>>((const float*)p_h1, (const float*)p_agg,
                                      Ws2, Wn2, b2, (float*)p_h2, n);

    // edge scores + min/max + normalize
    k_score<<<1184, 256>>>((const float*)p_h2, src, dst, out, e);
    k_norm<<<(e + tpb - 1) / tpb, tpb>>>(out, e);
}

// round 3
// speedup vs baseline: 1.0631x; 1.0631x over previous
#include <cuda_runtime.h>
#include <math.h>

#define NMAX 100000
#define EMAX 1600000
#define F 128

// ---------------- scratch (device globals: no allocation allowed) ----------
__device__ int   g_cnt[NMAX];                    // per-dst edge count
__device__ int   g_off[NMAX + 1];                // CSR offsets
__device__ int   g_pos[NMAX];                    // running fill positions
__device__ int   g_srcs[EMAX];                   // src ids grouped by dst
__device__ float g_deg[NMAX];                    // 1 / max(deg,1)
__device__ float g_agg[(size_t)NMAX * F];        // neighbor mean
__device__ float g_h1[(size_t)NMAX * F];
__device__ float g_h2[(size_t)NMAX * F];
__device__ unsigned int g_mm[2];                 // [0]=encoded min, [1]=encoded max

// order-preserving float -> uint encoding (for atomicMin/Max on floats)
__device__ __forceinline__ unsigned fenc(float f) {
    unsigned u = __float_as_uint(f);
    return (u & 0x80000000u) ? ~u : (u | 0x80000000u);
}
__device__ __forceinline__ float fdec(unsigned u) {
    return __uint_as_float((u & 0x80000000u) ? (u ^ 0x80000000u) : ~u);
}

// ---------------- packed f32x2 helpers (FFMA2: 2 fp32 FMA per instr) --------
__device__ __forceinline__ void fma2(unsigned long long& d,
                                     const unsigned long long a,
                                     const unsigned long long b) {
    asm("fma.rn.f32x2 %0, %1, %2, %0;" : "+l"(d) : "l"(a), "l"(b));
}
__device__ __forceinline__ unsigned long long pack2(float x) {
    unsigned long long r;
    asm("mov.b64 %0, {%1, %1};" : "=l"(r) : "f"(x));
    return r;
}
__device__ __forceinline__ float2 unpack2(unsigned long long v) {
    float2 f;
    asm("mov.b64 {%0, %1}, %2;" : "=f"(f.x), "=f"(f.y) : "l"(v));
    return f;
}

// ---------------- CSR build --------------------------------------------------
__global__ void k_count(const int* __restrict__ dst, int e) {
    int i = blockIdx.x * blockDim.x + threadIdx.x;
    if (i < e) atomicAdd(&g_cnt[dst[i]], 1);
}

// single block, 1024 threads: chunked exclusive scan + inv-degree
__global__ void k_scan(int n) {
    __shared__ int part[1024];
    int tid = threadIdx.x;
    int chunk = (n + 1023) / 1024;
    int b = tid * chunk;
    int s = 0;
    for (int i = 0; i < chunk; i++) {
        int idx = b + i;
        if (idx < n) s += g_cnt[idx];
    }
    part[tid] = s;
    __syncthreads();
    for (int o = 1; o < 1024; o <<= 1) {
        int v = (tid >= o) ? part[tid - o] : 0;
        __syncthreads();
        if (tid >= o) part[tid] += v;
        __syncthreads();
    }
    int run = tid ? part[tid - 1] : 0;
    for (int i = 0; i < chunk; i++) {
        int idx = b + i;
        if (idx < n) {
            int c = g_cnt[idx];
            g_off[idx] = run;
            g_pos[idx] = run;
            g_deg[idx] = 1.0f / fmaxf((float)c, 1.0f);
            run += c;
        }
    }
    if (tid == 1023) g_off[n] = run;
}

__global__ void k_fill(const int* __restrict__ src, const int* __restrict__ dst, int e) {
    int i = blockIdx.x * blockDim.x + threadIdx.x;
    if (i < e) {
        int p = atomicAdd(&g_pos[dst[i]], 1);
        g_srcs[p] = src[i];
    }
}

// ---------------- gather aggregation: warp per node, registers accumulate ---
__global__ void k_gather(const float* __restrict__ h, float* __restrict__ agg, int n) {
    int w = (blockIdx.x * blockDim.x + threadIdx.x) >> 5;
    if (w >= n) return;
    int lane = threadIdx.x & 31;
    int beg = g_off[w], end = g_off[w + 1];
    float4 acc = make_float4(0.f, 0.f, 0.f, 0.f);
    int j = beg;
    for (; j + 1 < end; j += 2) {
        int s0 = __ldg(g_srcs + j);
        int s1 = __ldg(g_srcs + j + 1);
        float4 v0 = __ldg((const float4*)h + (size_t)s0 * 32 + lane);
        float4 v1 = __ldg((const float4*)h + (size_t)s1 * 32 + lane);
        acc.x += v0.x; acc.y += v0.y; acc.z += v0.z; acc.w += v0.w;
        acc.x += v1.x; acc.y += v1.y; acc.z += v1.z; acc.w += v1.w;
    }
    if (j < end) {
        int s0 = __ldg(g_srcs + j);
        float4 v0 = __ldg((const float4*)h + (size_t)s0 * 32 + lane);
        acc.x += v0.x; acc.y += v0.y; acc.z += v0.z; acc.w += v0.w;
    }
    float inv = g_deg[w];
    acc.x *= inv; acc.y *= inv; acc.z *= inv; acc.w *= inv;
    ((float4*)agg)[(size_t)w * 32 + lane] = acc;
}

// ---------------- fused SAGE GEMM: out = A1@W1 + A2@W2 + bias (f32x2) -------
// [N,256] @ [256,128]. W staged in SMEM, transposed 64-row A tile in SMEM.
// Block 256 threads, 64 rows x 128 cols, 2x16 outputs/thread via FFMA2.
__global__ void __launch_bounds__(256, 1)
k_gemm(const float* __restrict__ A1, const float* __restrict__ A2,
       const float* __restrict__ W1, const float* __restrict__ W2,
       const float* __restrict__ bias, float* __restrict__ out, int n) {
    extern __shared__ float sm[];
    float* Ws = sm;               // [256][128]            = 128 KB
    float* As = sm + 256 * 128;   // [256][65] (k-major)   = 65 KB (padded)

    const int tid = threadIdx.x;
    const int tx = tid & 7;       // 8 column groups
    const int ty = tid >> 3;      // 32 row slots (rows ty and ty+32)
    const int base = blockIdx.x * 64;

    // stage W: rows 0..127 = W1, rows 128..255 = W2
    {
        const float4* w1 = (const float4*)W1;
        const float4* w2 = (const float4*)W2;
        float4* ws4 = (float4*)Ws;
        for (int i = tid; i < 8192; i += 256)
            ws4[i] = (i < 4096) ? __ldg(w1 + i) : __ldg(w2 + (i - 4096));
    }

    // stage A transposed: As[k][r]
    for (int i = tid; i < 64 * 64; i += 256) {
        int r  = i >> 6;
        int c4 = i & 63;
        int row = base + r;
        float4 v = make_float4(0.f, 0.f, 0.f, 0.f);
        if (row < n)
            v = (c4 < 32) ? __ldg((const float4*)A1 + (size_t)row * 32 + c4)
                          : __ldg((const float4*)A2 + (size_t)row * 32 + (c4 - 32));
        int k0 = c4 * 4;
        As[(k0 + 0) * 65 + r] = v.x;
        As[(k0 + 1) * 65 + r] = v.y;
        As[(k0 + 2) * 65 + r] = v.z;
        As[(k0 + 3) * 65 + r] = v.w;
    }
    __syncthreads();

    unsigned long long acc0[8], acc1[8];
#pragma unroll
    for (int j = 0; j < 8; j++) { acc0[j] = 0ull; acc1[j] = 0ull; }

#pragma unroll 4
    for (int k = 0; k < 256; ++k) {
        unsigned long long pa0 = pack2(As[k * 65 + ty]);
        unsigned long long pa1 = pack2(As[k * 65 + 32 + ty]);
        const ulonglong2* wr = (const ulonglong2*)(Ws + k * 128);
#pragma unroll
        for (int j = 0; j < 4; ++j) {
            ulonglong2 w = wr[tx + 8 * j];   // 16B: two f32x2 halves
            fma2(acc0[2 * j + 0], pa0, w.x);
            fma2(acc0[2 * j + 1], pa0, w.y);
            fma2(acc1[2 * j + 0], pa1, w.x);
            fma2(acc1[2 * j + 1], pa1, w.y);
        }
    }

    int row0 = base + ty;
    int row1 = base + 32 + ty;
#pragma unroll
    for (int j = 0; j < 4; ++j) {
        int c4 = tx + 8 * j;
        float4 bv = __ldg((const float4*)bias + c4);
        if (row0 < n) {
            float2 lo = unpack2(acc0[2 * j]), hi = unpack2(acc0[2 * j + 1]);
            float4 o = make_float4(lo.x + bv.x, lo.y + bv.y, hi.x + bv.z, hi.y + bv.w);
            ((float4*)out)[(size_t)row0 * 32 + c4] = o;
        }
        if (row1 < n) {
            float2 lo = unpack2(acc1[2 * j]), hi = unpack2(acc1[2 * j + 1]);
            float4 o = make_float4(lo.x + bv.x, lo.y + bv.y, hi.x + bv.z, hi.y + bv.w);
            ((float4*)out)[(size_t)row1 * 32 + c4] = o;
        }
    }
}

// ---------------- edge scores: warp per edge (grid-stride) + min/max --------
__global__ void k_score(const float* __restrict__ h, const int* __restrict__ src,
                        const int* __restrict__ dst, float* __restrict__ out, int e) {
    int gw = (blockIdx.x * blockDim.x + threadIdx.x) >> 5;
    int nw = (gridDim.x * blockDim.x) >> 5;
    int lane = threadIdx.x & 31;
    float lmin = 3.402823466e38f;
    float lmax = -3.402823466e38f;

    for (int i = gw; i < e; i += nw) {
        int s = __ldg(src + i);
        int d = __ldg(dst + i);
        float4 a = __ldg((const float4*)h + (size_t)s * 32 + lane);
        float4 b = __ldg((const float4*)h + (size_t)d * 32 + lane);
        float p = a.x * b.x + a.y * b.y + a.z * b.z + a.w * b.w;
#pragma unroll
        for (int o = 16; o; o >>= 1) p += __shfl_xor_sync(0xffffffffu, p, o);
        if (lane == 0) {
            out[i] = p;
            lmin = fminf(lmin, p);
            lmax = fmaxf(lmax, p);
        }
    }

#pragma unroll
    for (int o = 16; o; o >>= 1) {
        lmin = fminf(lmin, __shfl_xor_sync(0xffffffffu, lmin, o));
        lmax = fmaxf(lmax, __shfl_xor_sync(0xffffffffu, lmax, o));
    }
    __shared__ float smin[8], smax[8];
    int wid = threadIdx.x >> 5;
    if (lane == 0) { smin[wid] = lmin; smax[wid] = lmax; }
    __syncthreads();
    if (threadIdx.x == 0) {
        float m0 = smin[0], m1 = smax[0];
#pragma unroll
        for (int i = 1; i < 8; i++) { m0 = fminf(m0, smin[i]); m1 = fmaxf(m1, smax[i]); }
        atomicMin(&g_mm[0], fenc(m0));
        atomicMax(&g_mm[1], fenc(m1));
    }
}

__global__ void k_norm(float* __restrict__ out, int e) {
    int i = blockIdx.x * blockDim.x + threadIdx.x;
    if (i >= e) return;
    float mn = fdec(g_mm[0]);
    float mx = fdec(g_mm[1]);
    float inv = 1.0f / (mx - mn);
    out[i] = (out[i] - mn) * inv;
}

// ---------------- launch ------------------------------------------------------
extern "C" void kernel_launch(void* const* d_in, const int* in_sizes, int n_in,
                              void* d_out, int out_size) {
    const float* x   = (const float*)d_in[0];
    const int*   src = (const int*)d_in[1];
    const int*   dst = (const int*)d_in[2];
    const float* Ws1 = (const float*)d_in[3];
    const float* Wn1 = (const float*)d_in[4];
    const float* b1  = (const float*)d_in[5];
    const float* Ws2 = (const float*)d_in[6];
    const float* Wn2 = (const float*)d_in[7];
    const float* b2  = (const float*)d_in[8];
    float* out = (float*)d_out;

    int n = in_sizes[0] / F;
    int e = in_sizes[1];

    void *p_cnt, *p_agg, *p_h1, *p_h2, *p_mm;
    cudaGetSymbolAddress(&p_cnt, g_cnt);
    cudaGetSymbolAddress(&p_agg, g_agg);
    cudaGetSymbolAddress(&p_h1, g_h1);
    cudaGetSymbolAddress(&p_h2, g_h2);
    cudaGetSymbolAddress(&p_mm, g_mm);

    const int tpb = 256;
    const size_t SMEM = (256 * 128 + 256 * 65) * sizeof(float);  // 197,632 B
    cudaFuncSetAttribute(k_gemm, cudaFuncAttributeMaxDynamicSharedMemorySize, (int)SMEM);

    // init
    cudaMemsetAsync(p_cnt, 0, (size_t)n * sizeof(int), 0);
    cudaMemsetAsync(p_mm, 0xFF, 4, 0);                  // encoded min init
    cudaMemsetAsync((char*)p_mm + 4, 0x00, 4, 0);       // encoded max init

    // CSR build (by dst)
    k_count<<<(e + tpb - 1) / tpb, tpb>>>(dst, e);
    k_scan<<<1, 1024>>>(n);
    k_fill<<<(e + tpb - 1) / tpb, tpb>>>(src, dst, e);

    int gatherBlocks = (int)(((long)n * 32 + tpb - 1) / tpb);
    int gemmBlocks = (n + 63) / 64;

    // layer 1
    k_gather<<<gatherBlocks, tpb>>>(x, (float*)p_agg, n);
    k_gemm<<<gemmBlocks, 256, SMEM>>>(x, (const float*)p_agg, Ws1, Wn1, b1,
                                      (float*)p_h1, n);

    // layer 2
    k_gather<<<gatherBlocks, tpb>>>((const float*)p_h1, (float*)p_agg, n);
    k_gemm<<<gemmBlocks, 256, SMEM>>>((const float*)p_h1, (const float*)p_agg,
                                      Ws2, Wn2, b2, (float*)p_h2, n);

    // edge scores + min/max + normalize
    k_score<<<1184, 256>>>((const float*)p_h2, src, dst, out, e);
    k_norm<<<(e + tpb - 1) / tpb, tpb>>>(out, e);
}

// round 5
// speedup vs baseline: 1.6945x; 1.5939x over previous
#include <cuda_runtime.h>
#include <cuda_bf16.h>
#include <math.h>
#include <stdint.h>

#define NMAX 100000
#define EMAX 1600000
#define F 128
#define NB_MAX 782                       // ceil(100000/128)
#define AIMG 32768                       // one 128x128 bf16 fragment image

// ---------------- scratch (device globals) ----------------------------------
__device__ int   g_cnt[NMAX];
__device__ int   g_off[NMAX + 1];
__device__ int   g_pos[NMAX];
__device__ int   g_srcs[EMAX];
__device__ float g_deg[NMAX];
__device__ float g_h1[(size_t)NMAX * F];
__device__ float g_h2[(size_t)NMAX * F];
__device__ unsigned int g_mm[2];

// fragment-major bf16 images: A-type [nb][32768 B]
__device__ uint8_t g_Xhi[(size_t)NB_MAX * AIMG];
__device__ uint8_t g_Xlo[(size_t)NB_MAX * AIMG];
__device__ uint8_t g_AGhi[(size_t)NB_MAX * AIMG];
__device__ uint8_t g_AGlo[(size_t)NB_MAX * AIMG];
__device__ uint8_t g_H1hi[(size_t)NB_MAX * AIMG];
__device__ uint8_t g_H1lo[(size_t)NB_MAX * AIMG];
// W images: [layer][selfhi, selflo, neighhi, neighlo] x 32KB
__device__ uint8_t g_Wimg[2 * 4 * 32768];

// ---------------- helpers -----------------------------------------------------
__device__ __forceinline__ unsigned fenc(float f) {
    unsigned u = __float_as_uint(f);
    return (u & 0x80000000u) ? ~u : (u | 0x80000000u);
}
__device__ __forceinline__ float fdec(unsigned u) {
    return __uint_as_float((u & 0x80000000u) ? (u ^ 0x80000000u) : ~u);
}
__device__ __forceinline__ uint32_t pkf(float a, float b) {
    __nv_bfloat162 t = __floats2bfloat162_rn(a, b);   // .x = a (low half)
    return *(uint32_t*)&t;
}
// hi bf16x2 + residual bf16x2
__device__ __forceinline__ void split2(float a, float b, uint32_t& hi, uint32_t& lo) {
    __nv_bfloat16 ha = __float2bfloat16(a), hb = __float2bfloat16(b);
    __nv_bfloat162 h2 = __halves2bfloat162(ha, hb);
    hi = *(uint32_t*)&h2;
    lo = pkf(a - __bfloat162float(ha), b - __bfloat162float(hb));
}
__device__ __forceinline__ uint32_t smem_u32(const void* p) {
    uint32_t a;
    asm("{ .reg .u64 t; cvta.to.shared.u64 t, %1; cvt.u32.u64 %0, t; }" : "=r"(a) : "l"(p));
    return a;
}
__device__ __forceinline__ void cp16(uint32_t dst, const void* src) {
    asm volatile("cp.async.cg.shared.global [%0], [%1], 16;" :: "r"(dst), "l"(src));
}
__device__ __forceinline__ void mma_bf16(float* d, const uint4 a, const uint2 b) {
    asm volatile(
        "mma.sync.aligned.m16n8k16.row.col.f32.bf16.bf16.f32 "
        "{%0,%1,%2,%3}, {%4,%5,%6,%7}, {%8,%9}, {%0,%1,%2,%3};"
        : "+f"(d[0]), "+f"(d[1]), "+f"(d[2]), "+f"(d[3])
        : "r"(a.x), "r"(a.y), "r"(a.z), "r"(a.w), "r"(b.x), "r"(b.y));
}

// ---------------- CSR build --------------------------------------------------
__global__ void k_count(const int* __restrict__ dst, int e) {
    int i = blockIdx.x * blockDim.x + threadIdx.x;
    if (i < e) atomicAdd(&g_cnt[dst[i]], 1);
}

__global__ void k_scan(int n) {
    __shared__ int part[1024];
    int tid = threadIdx.x;
    int chunk = (n + 1023) / 1024;
    int b = tid * chunk;
    int s = 0;
    for (int i = 0; i < chunk; i++) {
        int idx = b + i;
        if (idx < n) s += g_cnt[idx];
    }
    part[tid] = s;
    __syncthreads();
    for (int o = 1; o < 1024; o <<= 1) {
        int v = (tid >= o) ? part[tid - o] : 0;
        __syncthreads();
        if (tid >= o) part[tid] += v;
        __syncthreads();
    }
    int run = tid ? part[tid - 1] : 0;
    for (int i = 0; i < chunk; i++) {
        int idx = b + i;
        if (idx < n) {
            int c = g_cnt[idx];
            g_off[idx] = run;
            g_pos[idx] = run;
            g_deg[idx] = 1.0f / fmaxf((float)c, 1.0f);
            run += c;
        }
    }
    if (tid == 1023) g_off[n] = run;
}

__global__ void k_fill(const int* __restrict__ src, const int* __restrict__ dst, int e) {
    int i = blockIdx.x * blockDim.x + threadIdx.x;
    if (i < e) {
        int p = atomicAdd(&g_pos[dst[i]], 1);
        g_srcs[p] = src[i];
    }
}

// ---------------- converters --------------------------------------------------
// x -> X fragment images. One thread per (b, tm, tk, lane) cell.
__global__ void k_convx(const float* __restrict__ x, int n, int nb) {
    int idx = blockIdx.x * blockDim.x + threadIdx.x;
    if (idx >= nb * 2048) return;
    int lane = idx & 31;
    int tk = (idx >> 5) & 7;
    int tm = (idx >> 8) & 7;
    int b  = idx >> 11;
    int g = lane >> 2, t = lane & 3;
    int row0 = b * 128 + tm * 16 + g;
    int row1 = row0 + 8;
    int k0 = tk * 16 + 2 * t;
    float2 a00 = make_float2(0.f, 0.f), a01 = a00, a10 = a00, a11 = a00;
    if (row0 < n) {
        a00 = __ldg((const float2*)(x + (size_t)row0 * F + k0));
        a01 = __ldg((const float2*)(x + (size_t)row0 * F + k0 + 8));
    }
    if (row1 < n) {
        a10 = __ldg((const float2*)(x + (size_t)row1 * F + k0));
        a11 = __ldg((const float2*)(x + (size_t)row1 * F + k0 + 8));
    }
    uint4 hi, lo;
    split2(a00.x, a00.y, hi.x, lo.x);   // r0: row g, low k
    split2(a10.x, a10.y, hi.y, lo.y);   // r1: row g+8, low k
    split2(a01.x, a01.y, hi.z, lo.z);   // r2: row g, k+8
    split2(a11.x, a11.y, hi.w, lo.w);   // r3
    size_t off = (size_t)b * AIMG + tm * 4096 + tk * 512 + lane * 16;
    *(uint4*)(g_Xhi + off) = hi;
    *(uint4*)(g_Xlo + off) = lo;
}

// W[k][n] fp32 -> B-fragment images. One thread per (mat, tk, tn, lane).
__global__ void k_convw(const float* __restrict__ Ws1, const float* __restrict__ Wn1,
                        const float* __restrict__ Ws2, const float* __restrict__ Wn2) {
    int idx = blockIdx.x * blockDim.x + threadIdx.x;
    if (idx >= 4 * 8 * 16 * 32) return;
    int lane = idx & 31;
    int tn = (idx >> 5) & 15;
    int tk = (idx >> 9) & 7;
    int m = idx >> 12;
    const float* W = (m == 0) ? Ws1 : (m == 1) ? Wn1 : (m == 2) ? Ws2 : Wn2;
    int g = lane >> 2, t = lane & 3;
    int nn = tn * 8 + g;
    int k0 = tk * 16 + 2 * t;
    float w00 = __ldg(W + k0 * F + nn);
    float w01 = __ldg(W + (k0 + 1) * F + nn);
    float w10 = __ldg(W + (k0 + 8) * F + nn);
    float w11 = __ldg(W + (k0 + 9) * F + nn);
    uint2 hi, lo;
    split2(w00, w01, hi.x, lo.x);       // b0
    split2(w10, w11, hi.y, lo.y);       // b1
    int layer = m >> 1, which = m & 1;  // which: 0=self, 1=neigh
    size_t base = (size_t)layer * 131072 + (size_t)which * 65536;
    size_t off = tk * 4096 + tn * 256 + lane * 8;
    *(uint2*)(g_Wimg + base + off) = hi;
    *(uint2*)(g_Wimg + base + 32768 + off) = lo;
}

// ---------------- gather: warp per node -> mean -> AG fragment image ---------
__global__ void k_gather(const float* __restrict__ h, uint8_t* __restrict__ img_hi,
                         uint8_t* __restrict__ img_lo, int n, int npad) {
    int w = (blockIdx.x * blockDim.x + threadIdx.x) >> 5;
    if (w >= npad) return;
    int lane = threadIdx.x & 31;
    float4 acc = make_float4(0.f, 0.f, 0.f, 0.f);
    if (w < n) {
        int beg = g_off[w], end = g_off[w + 1];
        int j = beg;
        for (; j + 1 < end; j += 2) {
            int s0 = __ldg(g_srcs + j);
            int s1 = __ldg(g_srcs + j + 1);
            float4 v0 = __ldg((const float4*)h + (size_t)s0 * 32 + lane);
            float4 v1 = __ldg((const float4*)h + (size_t)s1 * 32 + lane);
            acc.x += v0.x + v1.x; acc.y += v0.y + v1.y;
            acc.z += v0.z + v1.z; acc.w += v0.w + v1.w;
        }
        if (j < end) {
            int s0 = __ldg(g_srcs + j);
            float4 v0 = __ldg((const float4*)h + (size_t)s0 * 32 + lane);
            acc.x += v0.x; acc.y += v0.y; acc.z += v0.z; acc.w += v0.w;
        }
        float inv = g_deg[w];
        acc.x *= inv; acc.y *= inv; acc.z *= inv; acc.w *= inv;
    }
    // scatter two k-pairs into fragment image
    int b = w >> 7;
    int rr = w & 127;
    int tm = rr >> 4;
    int rl = rr & 15;
    int g = rl & 7, rs = rl >> 3;
#pragma unroll
    for (int q = 0; q < 2; q++) {
        int p = 2 * lane + q;                 // k-pair index 0..63
        float v0 = q ? acc.z : acc.x;
        float v1 = q ? acc.w : acc.y;
        int tk = p >> 3;
        int tc = p & 7;
        int t = tc & 3, kh = tc >> 2;
        int reg = kh * 2 + rs;
        int L = g * 4 + t;
        size_t off = (size_t)b * AIMG + tm * 4096 + tk * 512 + L * 16 + reg * 4;
        uint32_t hi, lo;
        split2(v0, v1, hi, lo);
        *(uint32_t*)(img_hi + off) = hi;
        *(uint32_t*)(img_lo + off) = lo;
    }
}

// ---------------- mma.sync GEMM ----------------------------------------------
// out[128b..][128] = Aself@Wself + Aneigh@Wneigh + bias, bf16 3-term split.
// 256 threads = 8 warps (2 M x 4 N), warp tile 64x32, mma m16n8k16.
__global__ void __launch_bounds__(256, 1)
k_mma(const uint8_t* __restrict__ Ash, const uint8_t* __restrict__ Asl,
      const uint8_t* __restrict__ Anh, const uint8_t* __restrict__ Anl,
      const uint8_t* __restrict__ Wbase, const float* __restrict__ bias,
      float* __restrict__ hout, uint8_t* __restrict__ Hhi, uint8_t* __restrict__ Hlo,
      int n) {
    extern __shared__ __align__(16) uint8_t sm[];   // 128KB: Ahi, Alo, Whi, Wlo
    const int tid = threadIdx.x;
    const int lane = tid & 31, wid = tid >> 5;
    const int warp_m = wid >> 2, warp_n = wid & 3;
    const size_t b = blockIdx.x;
    uint32_t sb = smem_u32(sm);

    float acc[4][4][4];
#pragma unroll
    for (int i = 0; i < 4; i++)
#pragma unroll
        for (int j = 0; j < 4; j++)
#pragma unroll
            for (int c = 0; c < 4; c++) acc[i][j][c] = 0.f;

    const uint8_t* asrc[2][2] = {{Ash, Asl}, {Anh, Anl}};

#pragma unroll
    for (int phase = 0; phase < 2; phase++) {
        __syncthreads();
        // stage: A hi (32KB), A lo, W hi, W lo
        {
            const uint8_t* s0 = asrc[phase][0] + b * AIMG + tid * 16;
            const uint8_t* s1 = asrc[phase][1] + b * AIMG + tid * 16;
            const uint8_t* s2 = Wbase + (size_t)phase * 65536 + tid * 16;
            const uint8_t* s3 = s2 + 32768;
            uint32_t d = sb + tid * 16;
#pragma unroll
            for (int i = 0; i < 8; i++) {
                cp16(d + i * 4096, s0 + i * 4096);
                cp16(d + 32768 + i * 4096, s1 + i * 4096);
                cp16(d + 65536 + i * 4096, s2 + i * 4096);
                cp16(d + 98304 + i * 4096, s3 + i * 4096);
            }
            asm volatile("cp.async.commit_group;");
            asm volatile("cp.async.wait_group 0;" ::: "memory");
        }
        __syncthreads();

#pragma unroll
        for (int term = 0; term < 3; term++) {
            const uint8_t* As = sm + ((term == 2) ? 32768 : 0);
            const uint8_t* Ws = sm + ((term == 1) ? 98304 : 65536);
#pragma unroll
            for (int tk = 0; tk < 8; tk++) {
                uint2 bf[4];
                uint4 af[4];
#pragma unroll
                for (int j = 0; j < 4; j++)
                    bf[j] = *(const uint2*)(Ws + tk * 4096 + (warp_n * 4 + j) * 256 + lane * 8);
#pragma unroll
                for (int i = 0; i < 4; i++)
                    af[i] = *(const uint4*)(As + (warp_m * 4 + i) * 4096 + tk * 512 + lane * 16);
#pragma unroll
                for (int i = 0; i < 4; i++)
#pragma unroll
                    for (int j = 0; j < 4; j++)
                        mma_bf16(acc[i][j], af[i], bf[j]);
            }
        }
    }

    // epilogue: bias, fp32 out, optional next-layer fragment image
    const int g = lane >> 2, t = lane & 3;
#pragma unroll
    for (int i = 0; i < 4; i++) {
        int tm = warp_m * 4 + i;
        int row0 = (int)b * 128 + tm * 16 + g;
        int row1 = row0 + 8;
        bool l0 = row0 < n, l1 = row1 < n;
#pragma unroll
        for (int j = 0; j < 4; j++) {
            int nb8 = (warp_n * 4 + j) * 8 + 2 * t;
            float2 bv = __ldg((const float2*)(bias + nb8));
            float c0 = l0 ? acc[i][j][0] + bv.x : 0.f;
            float c1 = l0 ? acc[i][j][1] + bv.y : 0.f;
            float c2 = l1 ? acc[i][j][2] + bv.x : 0.f;
            float c3 = l1 ? acc[i][j][3] + bv.y : 0.f;
            if (l0) *(float2*)(hout + (size_t)row0 * F + nb8) = make_float2(c0, c1);
            if (l1) *(float2*)(hout + (size_t)row1 * F + nb8) = make_float2(c2, c3);
            acc[i][j][0] = c0; acc[i][j][1] = c1; acc[i][j][2] = c2; acc[i][j][3] = c3;
        }
        if (Hhi) {
#pragma unroll
            for (int jj = 0; jj < 2; jj++) {
                int tkp = warp_n * 2 + jj;
                uint4 hi, lo;
                split2(acc[i][2 * jj][0], acc[i][2 * jj][1], hi.x, lo.x);      // r0
                split2(acc[i][2 * jj][2], acc[i][2 * jj][3], hi.y, lo.y);      // r1
                split2(acc[i][2 * jj + 1][0], acc[i][2 * jj + 1][1], hi.z, lo.z); // r2
                split2(acc[i][2 * jj + 1][2], acc[i][2 * jj + 1][3], hi.w, lo.w); // r3
                size_t off = b * AIMG + tm * 4096 + tkp * 512 + lane * 16;
                *(uint4*)(Hhi + off) = hi;
                *(uint4*)(Hlo + off) = lo;
            }
        }
    }
}

// ---------------- edge scores + min/max + normalize --------------------------
__global__ void k_score(const float* __restrict__ h, const int* __restrict__ src,
                        const int* __restrict__ dst, float* __restrict__ out, int e) {
    int gw = (blockIdx.x * blockDim.x + threadIdx.x) >> 5;
    int nw = (gridDim.x * blockDim.x) >> 5;
    int lane = threadIdx.x & 31;
    float lmin = 3.402823466e38f;
    float lmax = -3.402823466e38f;

    for (int i = gw; i < e; i += nw) {
        int s = __ldg(src + i);
        int d = __ldg(dst + i);
        float4 a = __ldg((const float4*)h + (size_t)s * 32 + lane);
        float4 b = __ldg((const float4*)h + (size_t)d * 32 + lane);
        float p = a.x * b.x + a.y * b.y + a.z * b.z + a.w * b.w;
#pragma unroll
        for (int o = 16; o; o >>= 1) p += __shfl_xor_sync(0xffffffffu, p, o);
        if (lane == 0) {
            out[i] = p;
            lmin = fminf(lmin, p);
            lmax = fmaxf(lmax, p);
        }
    }
#pragma unroll
    for (int o = 16; o; o >>= 1) {
        lmin = fminf(lmin, __shfl_xor_sync(0xffffffffu, lmin, o));
        lmax = fmaxf(lmax, __shfl_xor_sync(0xffffffffu, lmax, o));
    }
    __shared__ float smin[8], smax[8];
    int wid = threadIdx.x >> 5;
    if (lane == 0) { smin[wid] = lmin; smax[wid] = lmax; }
    __syncthreads();
    if (threadIdx.x == 0) {
        float m0 = smin[0], m1 = smax[0];
#pragma unroll
        for (int i = 1; i < 8; i++) { m0 = fminf(m0, smin[i]); m1 = fmaxf(m1, smax[i]); }
        atomicMin(&g_mm[0], fenc(m0));
        atomicMax(&g_mm[1], fenc(m1));
    }
}

__global__ void k_norm(float* __restrict__ out, int e) {
    int i = blockIdx.x * blockDim.x + threadIdx.x;
    if (i >= e) return;
    float mn = fdec(g_mm[0]);
    float mx = fdec(g_mm[1]);
    float inv = 1.0f / (mx - mn);
    out[i] = (out[i] - mn) * inv;
}

// ---------------- launch ------------------------------------------------------
extern "C" void kernel_launch(void* const* d_in, const int* in_sizes, int n_in,
                              void* d_out, int out_size) {
    const float* x   = (const float*)d_in[0];
    const int*   src = (const int*)d_in[1];
    const int*   dst = (const int*)d_in[2];
    const float* Ws1 = (const float*)d_in[3];
    const float* Wn1 = (const float*)d_in[4];
    const float* b1  = (const float*)d_in[5];
    const float* Ws2 = (const float*)d_in[6];
    const float* Wn2 = (const float*)d_in[7];
    const float* b2  = (const float*)d_in[8];
    float* out = (float*)d_out;

    int n = in_sizes[0] / F;
    int e = in_sizes[1];
    int nb = (n + 127) >> 7;
    int npad = nb * 128;

    void *p_cnt, *p_mm, *p_h1, *p_h2;
    void *p_Xhi, *p_Xlo, *p_AGhi, *p_AGlo, *p_H1hi, *p_H1lo, *p_W;
    cudaGetSymbolAddress(&p_cnt, g_cnt);
    cudaGetSymbolAddress(&p_mm, g_mm);
    cudaGetSymbolAddress(&p_h1, g_h1);
    cudaGetSymbolAddress(&p_h2, g_h2);
    cudaGetSymbolAddress(&p_Xhi, g_Xhi);
    cudaGetSymbolAddress(&p_Xlo, g_Xlo);
    cudaGetSymbolAddress(&p_AGhi, g_AGhi);
    cudaGetSymbolAddress(&p_AGlo, g_AGlo);
    cudaGetSymbolAddress(&p_H1hi, g_H1hi);
    cudaGetSymbolAddress(&p_H1lo, g_H1lo);
    cudaGetSymbolAddress(&p_W, g_Wimg);

    const int tpb = 256;
    const int SMEM = 131072;
    cudaFuncSetAttribute(k_mma, cudaFuncAttributeMaxDynamicSharedMemorySize, SMEM);

    cudaMemsetAsync(p_cnt, 0, (size_t)n * sizeof(int), 0);
    cudaMemsetAsync(p_mm, 0xFF, 4, 0);
    cudaMemsetAsync((char*)p_mm + 4, 0x00, 4, 0);

    // CSR build (by dst)
    k_count<<<(e + tpb - 1) / tpb, tpb>>>(dst, e);
    k_scan<<<1, 1024>>>(n);
    k_fill<<<(e + tpb - 1) / tpb, tpb>>>(src, dst, e);

    // conversions
    k_convx<<<(nb * 2048 + tpb - 1) / tpb, tpb>>>(x, n, nb);
    k_convw<<<(16384 + tpb - 1) / tpb, tpb>>>(Ws1, Wn1, Ws2, Wn2);

    int gatherBlocks = (npad * 32 + tpb - 1) / tpb;

    // layer 1
    k_gather<<<gatherBlocks, tpb>>>(x, (uint8_t*)p_AGhi, (uint8_t*)p_AGlo, n, npad);
    k_mma<<<nb, 256, SMEM>>>((const uint8_t*)p_Xhi, (const uint8_t*)p_Xlo,
                             (const uint8_t*)p_AGhi, (const uint8_t*)p_AGlo,
                             (const uint8_t*)p_W, b1, (float*)p_h1,
                             (uint8_t*)p_H1hi, (uint8_t*)p_H1lo, n);

    // layer 2
    k_gather<<<gatherBlocks, tpb>>>((const float*)p_h1, (uint8_t*)p_AGhi,
                                    (uint8_t*)p_AGlo, n, npad);
    k_mma<<<nb, 256, SMEM>>>((const uint8_t*)p_H1hi, (const uint8_t*)p_H1lo,
                             (const uint8_t*)p_AGhi, (const uint8_t*)p_AGlo,
                             (const uint8_t*)((char*)p_W + 131072), b2, (float*)p_h2,
                             (uint8_t*)0, (uint8_t*)0, n);

    // edge scores + min/max + normalize
    k_score<<<1184, 256>>>((const float*)p_h2, src, dst, out, e);
    k_norm<<<(e + tpb - 1) / tpb, tpb>>>(out, e);
}

// round 6
// speedup vs baseline: 2.3094x; 1.3628x over previous
#include <cuda_runtime.h>
#include <cuda_bf16.h>
#include <math.h>
#include <stdint.h>

#define NMAX 100000
#define EMAX 1600000
#define F 128
#define NB_MAX 782                       // ceil(100000/128)
#define AIMG 32768                       // one 128x128 bf16 fragment image

// ---------------- scratch (device globals) ----------------------------------
__device__ int   g_cnt[NMAX];
__device__ int   g_off[NMAX];
__device__ int   g_pos[NMAX];
__device__ int   g_total;
__device__ int   g_srcs[EMAX];
__device__ float g_deg[NMAX];
__device__ float g_agg[(size_t)NMAX * F];
__device__ float g_h1[(size_t)NMAX * F];
__device__ float g_h2[(size_t)NMAX * F];
__device__ unsigned int g_mm[2];

// fragment-major bf16 images: A-type [nb][32768 B]
__device__ uint8_t g_Xhi[(size_t)NB_MAX * AIMG];
__device__ uint8_t g_Xlo[(size_t)NB_MAX * AIMG];
__device__ uint8_t g_AGhi[(size_t)NB_MAX * AIMG];
__device__ uint8_t g_AGlo[(size_t)NB_MAX * AIMG];
__device__ uint8_t g_H1hi[(size_t)NB_MAX * AIMG];
__device__ uint8_t g_H1lo[(size_t)NB_MAX * AIMG];
// W images: [layer][ self(hi,lo), neigh(hi,lo) ], contiguous 128KB per layer
__device__ uint8_t g_Wimg[2 * 4 * 32768];

// ---------------- helpers -----------------------------------------------------
__device__ __forceinline__ unsigned fenc(float f) {
    unsigned u = __float_as_uint(f);
    return (u & 0x80000000u) ? ~u : (u | 0x80000000u);
}
__device__ __forceinline__ float fdec(unsigned u) {
    return __uint_as_float((u & 0x80000000u) ? (u ^ 0x80000000u) : ~u);
}
__device__ __forceinline__ uint32_t pkf(float a, float b) {
    __nv_bfloat162 t = __floats2bfloat162_rn(a, b);
    return *(uint32_t*)&t;
}
__device__ __forceinline__ void split2(float a, float b, uint32_t& hi, uint32_t& lo) {
    __nv_bfloat16 ha = __float2bfloat16(a), hb = __float2bfloat16(b);
    __nv_bfloat162 h2 = __halves2bfloat162(ha, hb);
    hi = *(uint32_t*)&h2;
    lo = pkf(a - __bfloat162float(ha), b - __bfloat162float(hb));
}
__device__ __forceinline__ uint32_t smem_u32(const void* p) {
    uint32_t a;
    asm("{ .reg .u64 t; cvta.to.shared.u64 t, %1; cvt.u32.u64 %0, t; }" : "=r"(a) : "l"(p));
    return a;
}
__device__ __forceinline__ void mb_init(uint32_t m, uint32_t c) {
    asm volatile("mbarrier.init.shared.b64 [%0], %1;" :: "r"(m), "r"(c) : "memory");
}
__device__ __forceinline__ void mb_extx(uint32_t m, uint32_t bytes) {
    asm volatile("mbarrier.arrive.expect_tx.shared.b64 _, [%0], %1;" :: "r"(m), "r"(bytes) : "memory");
}
__device__ __forceinline__ void mb_wait(uint32_t m, uint32_t parity) {
    asm volatile(
        "{\n\t.reg .pred P;\n\t"
        "WL_%=: mbarrier.try_wait.parity.shared::cta.b64 P, [%0], %1;\n\t"
        "@P bra WD_%=;\n\t bra WL_%=;\n\tWD_%=:\n\t}"
        :: "r"(m), "r"(parity) : "memory");
}
__device__ __forceinline__ void bulk_g2s(uint32_t dst, const void* src, uint32_t bytes, uint32_t mbar) {
    asm volatile("cp.async.bulk.shared::cta.global.mbarrier::complete_tx::bytes [%0], [%1], %2, [%3];"
                 :: "r"(dst), "l"(src), "r"(bytes), "r"(mbar) : "memory");
}
__device__ __forceinline__ void mma_bf16(float* d, const uint4 a, const uint2 b) {
    asm volatile(
        "mma.sync.aligned.m16n8k16.row.col.f32.bf16.bf16.f32 "
        "{%0,%1,%2,%3}, {%4,%5,%6,%7}, {%8,%9}, {%0,%1,%2,%3};"
        : "+f"(d[0]), "+f"(d[1]), "+f"(d[2]), "+f"(d[3])
        : "r"(a.x), "r"(a.y), "r"(a.z), "r"(a.w), "r"(b.x), "r"(b.y));
}

// ---------------- CSR build --------------------------------------------------
__global__ void k_count(const int* __restrict__ dst, int e) {
    int i = blockIdx.x * blockDim.x + threadIdx.x;
    if (i < e) atomicAdd(&g_cnt[dst[i]], 1);
}

// fully parallel offsets: block scan + atomic global base (segment order arbitrary)
__global__ void k_offsets(int n) {
    __shared__ int wsum[8];
    __shared__ int sbase;
    int i = blockIdx.x * blockDim.x + threadIdx.x;
    int lane = threadIdx.x & 31, wid = threadIdx.x >> 5;
    int c = (i < n) ? g_cnt[i] : 0;
    int v = c;
#pragma unroll
    for (int o = 1; o < 32; o <<= 1) {
        int t = __shfl_up_sync(0xffffffffu, v, o);
        if (lane >= o) v += t;
    }
    if (lane == 31) wsum[wid] = v;
    __syncthreads();
    if (wid == 0) {
        int s = (lane < 8) ? wsum[lane] : 0;
#pragma unroll
        for (int o = 1; o < 8; o <<= 1) {
            int t = __shfl_up_sync(0xffffffffu, s, o);
            if (lane >= o) s += t;
        }
        if (lane < 8) wsum[lane] = s;
        if (lane == 7) sbase = atomicAdd(&g_total, s);
    }
    __syncthreads();
    if (i < n) {
        int excl = sbase + v - c + (wid ? wsum[wid - 1] : 0);
        g_off[i] = excl;
        g_pos[i] = excl;
        g_deg[i] = 1.0f / fmaxf((float)c, 1.0f);
    }
}

__global__ void k_fill(const int* __restrict__ src, const int* __restrict__ dst, int e) {
    int i = blockIdx.x * blockDim.x + threadIdx.x;
    if (i < e) {
        int p = atomicAdd(&g_pos[dst[i]], 1);
        g_srcs[p] = src[i];
    }
}

// ---------------- converter: row-major fp32 -> A fragment images (hi/lo) ----
__global__ void k_conv(const float* __restrict__ x, uint8_t* __restrict__ dhi,
                       uint8_t* __restrict__ dlo, int n, int nb) {
    int idx = blockIdx.x * blockDim.x + threadIdx.x;
    if (idx >= nb * 2048) return;
    int lane = idx & 31;
    int tk = (idx >> 5) & 7;
    int tm = (idx >> 8) & 7;
    int b  = idx >> 11;
    int g = lane >> 2, t = lane & 3;
    int row0 = b * 128 + tm * 16 + g;
    int row1 = row0 + 8;
    int k0 = tk * 16 + 2 * t;
    float2 a00 = make_float2(0.f, 0.f), a01 = a00, a10 = a00, a11 = a00;
    if (row0 < n) {
        a00 = __ldg((const float2*)(x + (size_t)row0 * F + k0));
        a01 = __ldg((const float2*)(x + (size_t)row0 * F + k0 + 8));
    }
    if (row1 < n) {
        a10 = __ldg((const float2*)(x + (size_t)row1 * F + k0));
        a11 = __ldg((const float2*)(x + (size_t)row1 * F + k0 + 8));
    }
    uint4 hi, lo;
    split2(a00.x, a00.y, hi.x, lo.x);
    split2(a10.x, a10.y, hi.y, lo.y);
    split2(a01.x, a01.y, hi.z, lo.z);
    split2(a11.x, a11.y, hi.w, lo.w);
    size_t off = (size_t)b * AIMG + tm * 4096 + tk * 512 + lane * 16;
    *(uint4*)(dhi + off) = hi;
    *(uint4*)(dlo + off) = lo;
}

// W[k][n] fp32 -> B-fragment images
__global__ void k_convw(const float* __restrict__ Ws1, const float* __restrict__ Wn1,
                        const float* __restrict__ Ws2, const float* __restrict__ Wn2) {
    int idx = blockIdx.x * blockDim.x + threadIdx.x;
    if (idx >= 4 * 8 * 16 * 32) return;
    int lane = idx & 31;
    int tn = (idx >> 5) & 15;
    int tk = (idx >> 9) & 7;
    int m = idx >> 12;
    const float* W = (m == 0) ? Ws1 : (m == 1) ? Wn1 : (m == 2) ? Ws2 : Wn2;
    int g = lane >> 2, t = lane & 3;
    int nn = tn * 8 + g;
    int k0 = tk * 16 + 2 * t;
    float w00 = __ldg(W + k0 * F + nn);
    float w01 = __ldg(W + (k0 + 1) * F + nn);
    float w10 = __ldg(W + (k0 + 8) * F + nn);
    float w11 = __ldg(W + (k0 + 9) * F + nn);
    uint2 hi, lo;
    split2(w00, w01, hi.x, lo.x);
    split2(w10, w11, hi.y, lo.y);
    int layer = m >> 1, which = m & 1;
    size_t base = (size_t)layer * 131072 + (size_t)which * 65536;
    size_t off = tk * 4096 + tn * 256 + lane * 8;
    *(uint2*)(g_Wimg + base + off) = hi;
    *(uint2*)(g_Wimg + base + 32768 + off) = lo;
}

// ---------------- gather: warp per node -> coalesced row-major mean ----------
__global__ void k_gather(const float* __restrict__ h, int n) {
    int w = (blockIdx.x * blockDim.x + threadIdx.x) >> 5;
    if (w >= n) return;
    int lane = threadIdx.x & 31;
    int beg = g_off[w];
    int end = beg + g_cnt[w];
    float4 acc = make_float4(0.f, 0.f, 0.f, 0.f);
    int j = beg;
    for (; j + 1 < end; j += 2) {
        int s0 = __ldg(g_srcs + j);
        int s1 = __ldg(g_srcs + j + 1);
        float4 v0 = __ldg((const float4*)h + (size_t)s0 * 32 + lane);
        float4 v1 = __ldg((const float4*)h + (size_t)s1 * 32 + lane);
        acc.x += v0.x + v1.x; acc.y += v0.y + v1.y;
        acc.z += v0.z + v1.z; acc.w += v0.w + v1.w;
    }
    if (j < end) {
        int s0 = __ldg(g_srcs + j);
        float4 v0 = __ldg((const float4*)h + (size_t)s0 * 32 + lane);
        acc.x += v0.x; acc.y += v0.y; acc.z += v0.z; acc.w += v0.w;
    }
    float inv = g_deg[w];
    acc.x *= inv; acc.y *= inv; acc.z *= inv; acc.w *= inv;
    ((float4*)g_agg)[(size_t)w * 32 + lane] = acc;
}

// ---------------- mma.sync GEMM with cp.async.bulk staging -------------------
// out[128b..][128] = Aself@Wself + Aneigh@Wneigh + bias, bf16 3-term split.
// SMEM: [ctrl 1KB][W both phases 128KB][A 64KB] = 193.5KB, 1 block/SM.
__global__ void __launch_bounds__(256, 1)
k_mma(const uint8_t* __restrict__ Ash, const uint8_t* __restrict__ Asl,
      const uint8_t* __restrict__ Anh, const uint8_t* __restrict__ Anl,
      const uint8_t* __restrict__ Wbase, const float* __restrict__ bias,
      float* __restrict__ hout, uint8_t* __restrict__ Hhi, uint8_t* __restrict__ Hlo,
      int n) {
    extern __shared__ __align__(128) uint8_t sm[];
    const uint32_t WOFF = 1024, AOFF = 1024 + 131072;
    const int tid = threadIdx.x;
    const int lane = tid & 31, wid = tid >> 5;
    const int warp_m = wid >> 2, warp_n = wid & 3;
    const size_t b = blockIdx.x;
    uint32_t sb = smem_u32(sm);

    if (tid == 0) {
        mb_init(sb + 0, 1);
        mb_init(sb + 8, 1);
        asm volatile("fence.proxy.async.shared::cta;" ::: "memory");
    }
    __syncthreads();

    const uint8_t* asrc[2][2] = {{Ash, Asl}, {Anh, Anl}};

    if (tid == 0) {
        mb_extx(sb + 0, 131072 + 65536);
        bulk_g2s(sb + WOFF, Wbase, 131072, sb + 0);                    // W both phases
        bulk_g2s(sb + AOFF, asrc[0][0] + b * AIMG, 32768, sb + 0);     // A0 hi
        bulk_g2s(sb + AOFF + 32768, asrc[0][1] + b * AIMG, 32768, sb + 0);  // A0 lo
    }

    float acc[4][4][4];
#pragma unroll
    for (int i = 0; i < 4; i++)
#pragma unroll
        for (int j = 0; j < 4; j++)
#pragma unroll
            for (int c = 0; c < 4; c++) acc[i][j][c] = 0.f;

#pragma unroll
    for (int phase = 0; phase < 2; phase++) {
        mb_wait(sb + 8 * phase, 0);
        __syncthreads();

#pragma unroll
        for (int term = 0; term < 3; term++) {
            const uint8_t* As = sm + AOFF + ((term == 2) ? 32768 : 0);
            const uint8_t* Ws = sm + WOFF + phase * 65536 + ((term == 1) ? 32768 : 0);
#pragma unroll
            for (int tk = 0; tk < 8; tk++) {
                uint2 bf[4];
                uint4 af[4];
#pragma unroll
                for (int j = 0; j < 4; j++)
                    bf[j] = *(const uint2*)(Ws + tk * 4096 + (warp_n * 4 + j) * 256 + lane * 8);
#pragma unroll
                for (int i = 0; i < 4; i++)
                    af[i] = *(const uint4*)(As + (warp_m * 4 + i) * 4096 + tk * 512 + lane * 16);
#pragma unroll
                for (int i = 0; i < 4; i++)
#pragma unroll
                    for (int j = 0; j < 4; j++)
                        mma_bf16(acc[i][j], af[i], bf[j]);
            }
        }
        if (phase == 0) {
            __syncthreads();            // everyone done reading A buffer
            if (tid == 0) {
                mb_extx(sb + 8, 65536);
                bulk_g2s(sb + AOFF, asrc[1][0] + b * AIMG, 32768, sb + 8);
                bulk_g2s(sb + AOFF + 32768, asrc[1][1] + b * AIMG, 32768, sb + 8);
            }
        }
    }

    // epilogue: bias, fp32 out, optional next-layer fragment image
    const int g = lane >> 2, t = lane & 3;
#pragma unroll
    for (int i = 0; i < 4; i++) {
        int tm = warp_m * 4 + i;
        int row0 = (int)b * 128 + tm * 16 + g;
        int row1 = row0 + 8;
        bool l0 = row0 < n, l1 = row1 < n;
#pragma unroll
        for (int j = 0; j < 4; j++) {
            int nb8 = (warp_n * 4 + j) * 8 + 2 * t;
            float2 bv = __ldg((const float2*)(bias + nb8));
            float c0 = l0 ? acc[i][j][0] + bv.x : 0.f;
            float c1 = l0 ? acc[i][j][1] + bv.y : 0.f;
            float c2 = l1 ? acc[i][j][2] + bv.x : 0.f;
            float c3 = l1 ? acc[i][j][3] + bv.y : 0.f;
            if (l0) *(float2*)(hout + (size_t)row0 * F + nb8) = make_float2(c0, c1);
            if (l1) *(float2*)(hout + (size_t)row1 * F + nb8) = make_float2(c2, c3);
            acc[i][j][0] = c0; acc[i][j][1] = c1; acc[i][j][2] = c2; acc[i][j][3] = c3;
        }
        if (Hhi) {
#pragma unroll
            for (int jj = 0; jj < 2; jj++) {
                int tkp = warp_n * 2 + jj;
                uint4 hi, lo;
                split2(acc[i][2 * jj][0], acc[i][2 * jj][1], hi.x, lo.x);
                split2(acc[i][2 * jj][2], acc[i][2 * jj][3], hi.y, lo.y);
                split2(acc[i][2 * jj + 1][0], acc[i][2 * jj + 1][1], hi.z, lo.z);
                split2(acc[i][2 * jj + 1][2], acc[i][2 * jj + 1][3], hi.w, lo.w);
                size_t off = b * AIMG + tm * 4096 + tkp * 512 + lane * 16;
                *(uint4*)(Hhi + off) = hi;
                *(uint4*)(Hlo + off) = lo;
            }
        }
    }
}

// ---------------- edge scores + min/max + normalize --------------------------
__global__ void k_score(const float* __restrict__ h, const int* __restrict__ src,
                        const int* __restrict__ dst, float* __restrict__ out, int e) {
    int gw = (blockIdx.x * blockDim.x + threadIdx.x) >> 5;
    int nw = (gridDim.x * blockDim.x) >> 5;
    int lane = threadIdx.x & 31;
    float lmin = 3.402823466e38f;
    float lmax = -3.402823466e38f;

    for (int i = gw; i < e; i += nw) {
        int s = __ldg(src + i);
        int d = __ldg(dst + i);
        float4 a = __ldg((const float4*)h + (size_t)s * 32 + lane);
        float4 b = __ldg((const float4*)h + (size_t)d * 32 + lane);
        float p = a.x * b.x + a.y * b.y + a.z * b.z + a.w * b.w;
#pragma unroll
        for (int o = 16; o; o >>= 1) p += __shfl_xor_sync(0xffffffffu, p, o);
        if (lane == 0) {
            out[i] = p;
            lmin = fminf(lmin, p);
            lmax = fmaxf(lmax, p);
        }
    }
#pragma unroll
    for (int o = 16; o; o >>= 1) {
        lmin = fminf(lmin, __shfl_xor_sync(0xffffffffu, lmin, o));
        lmax = fmaxf(lmax, __shfl_xor_sync(0xffffffffu, lmax, o));
    }
    __shared__ float smin[8], smax[8];
    int wid = threadIdx.x >> 5;
    if (lane == 0) { smin[wid] = lmin; smax[wid] = lmax; }
    __syncthreads();
    if (threadIdx.x == 0) {
        float m0 = smin[0], m1 = smax[0];
#pragma unroll
        for (int i = 1; i < 8; i++) { m0 = fminf(m0, smin[i]); m1 = fmaxf(m1, smax[i]); }
        atomicMin(&g_mm[0], fenc(m0));
        atomicMax(&g_mm[1], fenc(m1));
    }
}

__global__ void k_norm(float* __restrict__ out, int e) {
    int i = blockIdx.x * blockDim.x + threadIdx.x;
    if (i >= e) return;
    float mn = fdec(g_mm[0]);
    float mx = fdec(g_mm[1]);
    float inv = 1.0f / (mx - mn);
    out[i] = (out[i] - mn) * inv;
}

// ---------------- launch ------------------------------------------------------
extern "C" void kernel_launch(void* const* d_in, const int* in_sizes, int n_in,
                              void* d_out, int out_size) {
    const float* x   = (const float*)d_in[0];
    const int*   src = (const int*)d_in[1];
    const int*   dst = (const int*)d_in[2];
    const float* Ws1 = (const float*)d_in[3];
    const float* Wn1 = (const float*)d_in[4];
    const float* b1  = (const float*)d_in[5];
    const float* Ws2 = (const float*)d_in[6];
    const float* Wn2 = (const float*)d_in[7];
    const float* b2  = (const float*)d_in[8];
    float* out = (float*)d_out;

    int n = in_sizes[0] / F;
    int e = in_sizes[1];
    int nb = (n + 127) >> 7;

    void *p_cnt, *p_mm, *p_tot, *p_h1, *p_h2, *p_agg;
    void *p_Xhi, *p_Xlo, *p_AGhi, *p_AGlo, *p_H1hi, *p_H1lo, *p_W;
    cudaGetSymbolAddress(&p_cnt, g_cnt);
    cudaGetSymbolAddress(&p_mm, g_mm);
    cudaGetSymbolAddress(&p_tot, g_total);
    cudaGetSymbolAddress(&p_h1, g_h1);
    cudaGetSymbolAddress(&p_h2, g_h2);
    cudaGetSymbolAddress(&p_agg, g_agg);
    cudaGetSymbolAddress(&p_Xhi, g_Xhi);
    cudaGetSymbolAddress(&p_Xlo, g_Xlo);
    cudaGetSymbolAddress(&p_AGhi, g_AGhi);
    cudaGetSymbolAddress(&p_AGlo, g_AGlo);
    cudaGetSymbolAddress(&p_H1hi, g_H1hi);
    cudaGetSymbolAddress(&p_H1lo, g_H1lo);
    cudaGetSymbolAddress(&p_W, g_Wimg);

    const int tpb = 256;
    const int SMEM = 1024 + 131072 + 65536;   // 197,632 B
    cudaFuncSetAttribute(k_mma, cudaFuncAttributeMaxDynamicSharedMemorySize, SMEM);

    cudaMemsetAsync(p_cnt, 0, (size_t)n * sizeof(int), 0);
    cudaMemsetAsync(p_tot, 0, 4, 0);
    cudaMemsetAsync(p_mm, 0xFF, 4, 0);
    cudaMemsetAsync((char*)p_mm + 4, 0x00, 4, 0);

    // CSR build (by dst)
    k_count<<<(e + tpb - 1) / tpb, tpb>>>(dst, e);
    k_offsets<<<(n + tpb - 1) / tpb, tpb>>>(n);
    k_fill<<<(e + tpb - 1) / tpb, tpb>>>(src, dst, e);

    // conversions
    k_conv<<<(nb * 2048 + tpb - 1) / tpb, tpb>>>(x, (uint8_t*)p_Xhi, (uint8_t*)p_Xlo, n, nb);
    k_convw<<<(16384 + tpb - 1) / tpb, tpb>>>(Ws1, Wn1, Ws2, Wn2);

    int gatherBlocks = ((n * 32) + tpb - 1) / tpb;

    // layer 1
    k_gather<<<gatherBlocks, tpb>>>(x, n);
    k_conv<<<(nb * 2048 + tpb - 1) / tpb, tpb>>>((const float*)p_agg,
                                                 (uint8_t*)p_AGhi, (uint8_t*)p_AGlo, n, nb);
    k_mma<<<nb, 256, SMEM>>>((const uint8_t*)p_Xhi, (const uint8_t*)p_Xlo,
                             (const uint8_t*)p_AGhi, (const uint8_t*)p_AGlo,
                             (const uint8_t*)p_W, b1, (float*)p_h1,
                             (uint8_t*)p_H1hi, (uint8_t*)p_H1lo, n);

    // layer 2
    k_gather<<<gatherBlocks, tpb>>>((const float*)p_h1, n);
    k_conv<<<(nb * 2048 + tpb - 1) / tpb, tpb>>>((const float*)p_agg,
                                                 (uint8_t*)p_AGhi, (uint8_t*)p_AGlo, n, nb);
    k_mma<<<nb, 256, SMEM>>>((const uint8_t*)p_H1hi, (const uint8_t*)p_H1lo,
                             (const uint8_t*)p_AGhi, (const uint8_t*)p_AGlo,
                             (const uint8_t*)((char*)p_W + 131072), b2, (float*)p_h2,
                             (uint8_t*)0, (uint8_t*)0, n);

    // edge scores + min/max + normalize
    k_score<<<1184, 256>>>((const float*)p_h2, src, dst, out, e);
    k_norm<<<(e + tpb - 1) / tpb, tpb>>>(out, e);
}

// round 7
// speedup vs baseline: 2.7587x; 1.1946x over previous
#include <cuda_runtime.h>
#include <cuda_bf16.h>
#include <math.h>
#include <stdint.h>

#define NMAX 100000
#define EMAX 1600000
#define F 128
#define NB_MAX 782                       // ceil(100000/128)
#define AIMG 32768                       // one 128x128 bf16 fragment image

// ---------------- scratch (device globals) ----------------------------------
__device__ int   g_cnt[NMAX];
__device__ int   g_off[NMAX];
__device__ int   g_pos[NMAX];
__device__ int   g_total;
__device__ int   g_srcs[EMAX];
__device__ int   g_eidx[EMAX];
__device__ float g_deg[NMAX];
__device__ float g_agg[(size_t)NMAX * F];
__device__ float g_h1[(size_t)NMAX * F];
__device__ float g_h2[(size_t)NMAX * F];
__device__ unsigned int g_mm[2];

// fragment-major bf16 images: A-type [nb][32768 B]
__device__ uint8_t g_Xhi[(size_t)NB_MAX * AIMG];
__device__ uint8_t g_Xlo[(size_t)NB_MAX * AIMG];
__device__ uint8_t g_AGhi[(size_t)NB_MAX * AIMG];
__device__ uint8_t g_AGlo[(size_t)NB_MAX * AIMG];
__device__ uint8_t g_H1hi[(size_t)NB_MAX * AIMG];
__device__ uint8_t g_H1lo[(size_t)NB_MAX * AIMG];
// W images: [layer][ self(hi,lo), neigh(hi,lo) ], contiguous 128KB per layer
__device__ uint8_t g_Wimg[2 * 4 * 32768];

// ---------------- helpers -----------------------------------------------------
__device__ __forceinline__ unsigned fenc(float f) {
    unsigned u = __float_as_uint(f);
    return (u & 0x80000000u) ? ~u : (u | 0x80000000u);
}
__device__ __forceinline__ float fdec(unsigned u) {
    return __uint_as_float((u & 0x80000000u) ? (u ^ 0x80000000u) : ~u);
}
__device__ __forceinline__ uint32_t pkf(float a, float b) {
    __nv_bfloat162 t = __floats2bfloat162_rn(a, b);
    return *(uint32_t*)&t;
}
__device__ __forceinline__ void split2(float a, float b, uint32_t& hi, uint32_t& lo) {
    __nv_bfloat16 ha = __float2bfloat16(a), hb = __float2bfloat16(b);
    __nv_bfloat162 h2 = __halves2bfloat162(ha, hb);
    hi = *(uint32_t*)&h2;
    lo = pkf(a - __bfloat162float(ha), b - __bfloat162float(hb));
}
__device__ __forceinline__ uint32_t smem_u32(const void* p) {
    uint32_t a;
    asm("{ .reg .u64 t; cvta.to.shared.u64 t, %1; cvt.u32.u64 %0, t; }" : "=r"(a) : "l"(p));
    return a;
}
__device__ __forceinline__ void mb_init(uint32_t m, uint32_t c) {
    asm volatile("mbarrier.init.shared.b64 [%0], %1;" :: "r"(m), "r"(c) : "memory");
}
__device__ __forceinline__ void mb_extx(uint32_t m, uint32_t bytes) {
    asm volatile("mbarrier.arrive.expect_tx.shared.b64 _, [%0], %1;" :: "r"(m), "r"(bytes) : "memory");
}
__device__ __forceinline__ void mb_wait(uint32_t m, uint32_t parity) {
    asm volatile(
        "{\n\t.reg .pred P;\n\t"
        "WL_%=: mbarrier.try_wait.parity.shared::cta.b64 P, [%0], %1;\n\t"
        "@P bra WD_%=;\n\t bra WL_%=;\n\tWD_%=:\n\t}"
        :: "r"(m), "r"(parity) : "memory");
}
__device__ __forceinline__ void bulk_g2s(uint32_t dst, const void* src, uint32_t bytes, uint32_t mbar) {
    asm volatile("cp.async.bulk.shared::cta.global.mbarrier::complete_tx::bytes [%0], [%1], %2, [%3];"
                 :: "r"(dst), "l"(src), "r"(bytes), "r"(mbar) : "memory");
}
__device__ __forceinline__ void mma_bf16(float* d, const uint4 a, const uint2 b) {
    asm volatile(
        "mma.sync.aligned.m16n8k16.row.col.f32.bf16.bf16.f32 "
        "{%0,%1,%2,%3}, {%4,%5,%6,%7}, {%8,%9}, {%0,%1,%2,%3};"
        : "+f"(d[0]), "+f"(d[1]), "+f"(d[2]), "+f"(d[3])
        : "r"(a.x), "r"(a.y), "r"(a.z), "r"(a.w), "r"(b.x), "r"(b.y));
}

// ---------------- CSR build --------------------------------------------------
__global__ void k_count(const int* __restrict__ dst, int e) {
    int i = blockIdx.x * blockDim.x + threadIdx.x;
    if (i < e) atomicAdd(&g_cnt[dst[i]], 1);
}

// fully parallel offsets: block scan + atomic global base (segment order arbitrary)
__global__ void k_offsets(int n) {
    __shared__ int wsum[8];
    __shared__ int sbase;
    int i = blockIdx.x * blockDim.x + threadIdx.x;
    int lane = threadIdx.x & 31, wid = threadIdx.x >> 5;
    int c = (i < n) ? g_cnt[i] : 0;
    int v = c;
#pragma unroll
    for (int o = 1; o < 32; o <<= 1) {
        int t = __shfl_up_sync(0xffffffffu, v, o);
        if (lane >= o) v += t;
    }
    if (lane == 31) wsum[wid] = v;
    __syncthreads();
    if (wid == 0) {
        int s = (lane < 8) ? wsum[lane] : 0;
#pragma unroll
        for (int o = 1; o < 8; o <<= 1) {
            int t = __shfl_up_sync(0xffffffffu, s, o);
            if (lane >= o) s += t;
        }
        if (lane < 8) wsum[lane] = s;
        if (lane == 7) sbase = atomicAdd(&g_total, s);
    }
    __syncthreads();
    if (i < n) {
        int excl = sbase + v - c + (wid ? wsum[wid - 1] : 0);
        g_off[i] = excl;
        g_pos[i] = excl;
        g_deg[i] = 1.0f / fmaxf((float)c, 1.0f);
    }
}

__global__ void k_fill(const int* __restrict__ src, const int* __restrict__ dst, int e) {
    int i = blockIdx.x * blockDim.x + threadIdx.x;
    if (i < e) {
        int p = atomicAdd(&g_pos[dst[i]], 1);
        g_srcs[p] = src[i];
        g_eidx[p] = i;
    }
}

// ---------------- converter: row-major fp32 -> A fragment images (hi/lo) ----
__global__ void k_conv(const float* __restrict__ x, uint8_t* __restrict__ dhi,
                       uint8_t* __restrict__ dlo, int n, int nb) {
    int idx = blockIdx.x * blockDim.x + threadIdx.x;
    if (idx >= nb * 2048) return;
    int lane = idx & 31;
    int tk = (idx >> 5) & 7;
    int tm = (idx >> 8) & 7;
    int b  = idx >> 11;
    int g = lane >> 2, t = lane & 3;
    int row0 = b * 128 + tm * 16 + g;
    int row1 = row0 + 8;
    int k0 = tk * 16 + 2 * t;
    float2 a00 = make_float2(0.f, 0.f), a01 = a00, a10 = a00, a11 = a00;
    if (row0 < n) {
        a00 = __ldg((const float2*)(x + (size_t)row0 * F + k0));
        a01 = __ldg((const float2*)(x + (size_t)row0 * F + k0 + 8));
    }
    if (row1 < n) {
        a10 = __ldg((const float2*)(x + (size_t)row1 * F + k0));
        a11 = __ldg((const float2*)(x + (size_t)row1 * F + k0 + 8));
    }
    uint4 hi, lo;
    split2(a00.x, a00.y, hi.x, lo.x);
    split2(a10.x, a10.y, hi.y, lo.y);
    split2(a01.x, a01.y, hi.z, lo.z);
    split2(a11.x, a11.y, hi.w, lo.w);
    size_t off = (size_t)b * AIMG + tm * 4096 + tk * 512 + lane * 16;
    *(uint4*)(dhi + off) = hi;
    *(uint4*)(dlo + off) = lo;
}

// W[k][n] fp32 -> B-fragment images
__global__ void k_convw(const float* __restrict__ Ws1, const float* __restrict__ Wn1,
                        const float* __restrict__ Ws2, const float* __restrict__ Wn2) {
    int idx = blockIdx.x * blockDim.x + threadIdx.x;
    if (idx >= 4 * 8 * 16 * 32) return;
    int lane = idx & 31;
    int tn = (idx >> 5) & 15;
    int tk = (idx >> 9) & 7;
    int m = idx >> 12;
    const float* W = (m == 0) ? Ws1 : (m == 1) ? Wn1 : (m == 2) ? Ws2 : Wn2;
    int g = lane >> 2, t = lane & 3;
    int nn = tn * 8 + g;
    int k0 = tk * 16 + 2 * t;
    float w00 = __ldg(W + k0 * F + nn);
    float w01 = __ldg(W + (k0 + 1) * F + nn);
    float w10 = __ldg(W + (k0 + 8) * F + nn);
    float w11 = __ldg(W + (k0 + 9) * F + nn);
    uint2 hi, lo;
    split2(w00, w01, hi.x, lo.x);
    split2(w10, w11, hi.y, lo.y);
    int layer = m >> 1, which = m & 1;
    size_t base = (size_t)layer * 131072 + (size_t)which * 65536;
    size_t off = tk * 4096 + tn * 256 + lane * 8;
    *(uint2*)(g_Wimg + base + off) = hi;
    *(uint2*)(g_Wimg + base + 32768 + off) = lo;
}

// ---------------- gather: warp per node -> coalesced row-major mean ----------
__global__ void k_gather(const float* __restrict__ h, int n) {
    int w = (blockIdx.x * blockDim.x + threadIdx.x) >> 5;
    if (w >= n) return;
    int lane = threadIdx.x & 31;
    int beg = g_off[w];
    int end = beg + g_cnt[w];
    float4 acc = make_float4(0.f, 0.f, 0.f, 0.f);
    int j = beg;
    for (; j + 1 < end; j += 2) {
        int s0 = __ldg(g_srcs + j);
        int s1 = __ldg(g_srcs + j + 1);
        float4 v0 = __ldg((const float4*)h + (size_t)s0 * 32 + lane);
        float4 v1 = __ldg((const float4*)h + (size_t)s1 * 32 + lane);
        acc.x += v0.x + v1.x; acc.y += v0.y + v1.y;
        acc.z += v0.z + v1.z; acc.w += v0.w + v1.w;
    }
    if (j < end) {
        int s0 = __ldg(g_srcs + j);
        float4 v0 = __ldg((const float4*)h + (size_t)s0 * 32 + lane);
        acc.x += v0.x; acc.y += v0.y; acc.z += v0.z; acc.w += v0.w;
    }
    float inv = g_deg[w];
    acc.x *= inv; acc.y *= inv; acc.z *= inv; acc.w *= inv;
    ((float4*)g_agg)[(size_t)w * 32 + lane] = acc;
}

// ---------------- mma.sync GEMM with cp.async.bulk staging -------------------
__global__ void __launch_bounds__(256, 1)
k_mma(const uint8_t* __restrict__ Ash, const uint8_t* __restrict__ Asl,
      const uint8_t* __restrict__ Anh, const uint8_t* __restrict__ Anl,
      const uint8_t* __restrict__ Wbase, const float* __restrict__ bias,
      float* __restrict__ hout, uint8_t* __restrict__ Hhi, uint8_t* __restrict__ Hlo,
      int n) {
    extern __shared__ __align__(128) uint8_t sm[];
    const uint32_t WOFF = 1024, AOFF = 1024 + 131072;
    const int tid = threadIdx.x;
    const int lane = tid & 31, wid = tid >> 5;
    const int warp_m = wid >> 2, warp_n = wid & 3;
    const size_t b = blockIdx.x;
    uint32_t sb = smem_u32(sm);

    if (tid == 0) {
        mb_init(sb + 0, 1);
        mb_init(sb + 8, 1);
        asm volatile("fence.proxy.async.shared::cta;" ::: "memory");
    }
    __syncthreads();

    const uint8_t* asrc[2][2] = {{Ash, Asl}, {Anh, Anl}};

    if (tid == 0) {
        mb_extx(sb + 0, 131072 + 65536);
        bulk_g2s(sb + WOFF, Wbase, 131072, sb + 0);
        bulk_g2s(sb + AOFF, asrc[0][0] + b * AIMG, 32768, sb + 0);
        bulk_g2s(sb + AOFF + 32768, asrc[0][1] + b * AIMG, 32768, sb + 0);
    }

    float acc[4][4][4];
#pragma unroll
    for (int i = 0; i < 4; i++)
#pragma unroll
        for (int j = 0; j < 4; j++)
#pragma unroll
            for (int c = 0; c < 4; c++) acc[i][j][c] = 0.f;

#pragma unroll
    for (int phase = 0; phase < 2; phase++) {
        mb_wait(sb + 8 * phase, 0);
        __syncthreads();

#pragma unroll
        for (int term = 0; term < 3; term++) {
            const uint8_t* As = sm + AOFF + ((term == 2) ? 32768 : 0);
            const uint8_t* Ws = sm + WOFF + phase * 65536 + ((term == 1) ? 32768 : 0);
#pragma unroll
            for (int tk = 0; tk < 8; tk++) {
                uint2 bf[4];
                uint4 af[4];
#pragma unroll
                for (int j = 0; j < 4; j++)
                    bf[j] = *(const uint2*)(Ws + tk * 4096 + (warp_n * 4 + j) * 256 + lane * 8);
#pragma unroll
                for (int i = 0; i < 4; i++)
                    af[i] = *(const uint4*)(As + (warp_m * 4 + i) * 4096 + tk * 512 + lane * 16);
#pragma unroll
                for (int i = 0; i < 4; i++)
#pragma unroll
                    for (int j = 0; j < 4; j++)
                        mma_bf16(acc[i][j], af[i], bf[j]);
            }
        }
        if (phase == 0) {
            __syncthreads();
            if (tid == 0) {
                mb_extx(sb + 8, 65536);
                bulk_g2s(sb + AOFF, asrc[1][0] + b * AIMG, 32768, sb + 8);
                bulk_g2s(sb + AOFF + 32768, asrc[1][1] + b * AIMG, 32768, sb + 8);
            }
        }
    }

    // epilogue
    const int g = lane >> 2, t = lane & 3;
#pragma unroll
    for (int i = 0; i < 4; i++) {
        int tm = warp_m * 4 + i;
        int row0 = (int)b * 128 + tm * 16 + g;
        int row1 = row0 + 8;
        bool l0 = row0 < n, l1 = row1 < n;
#pragma unroll
        for (int j = 0; j < 4; j++) {
            int nb8 = (warp_n * 4 + j) * 8 + 2 * t;
            float2 bv = __ldg((const float2*)(bias + nb8));
            float c0 = l0 ? acc[i][j][0] + bv.x : 0.f;
            float c1 = l0 ? acc[i][j][1] + bv.y : 0.f;
            float c2 = l1 ? acc[i][j][2] + bv.x : 0.f;
            float c3 = l1 ? acc[i][j][3] + bv.y : 0.f;
            if (l0) *(float2*)(hout + (size_t)row0 * F + nb8) = make_float2(c0, c1);
            if (l1) *(float2*)(hout + (size_t)row1 * F + nb8) = make_float2(c2, c3);
            acc[i][j][0] = c0; acc[i][j][1] = c1; acc[i][j][2] = c2; acc[i][j][3] = c3;
        }
        if (Hhi) {
#pragma unroll
            for (int jj = 0; jj < 2; jj++) {
                int tkp = warp_n * 2 + jj;
                uint4 hi, lo;
                split2(acc[i][2 * jj][0], acc[i][2 * jj][1], hi.x, lo.x);
                split2(acc[i][2 * jj][2], acc[i][2 * jj][3], hi.y, lo.y);
                split2(acc[i][2 * jj + 1][0], acc[i][2 * jj + 1][1], hi.z, lo.z);
                split2(acc[i][2 * jj + 1][2], acc[i][2 * jj + 1][3], hi.w, lo.w);
                size_t off = b * AIMG + tm * 4096 + tkp * 512 + lane * 16;
                *(uint4*)(Hhi + off) = hi;
                *(uint4*)(Hlo + off) = lo;
            }
        }
    }
}

// ---------------- CSR edge scores: warp per node, dst row register-resident --
__global__ void k_score(const float* __restrict__ h, float* __restrict__ out, int n) {
    int w = (blockIdx.x * blockDim.x + threadIdx.x) >> 5;
    int lane = threadIdx.x & 31;
    float lmin = 3.402823466e38f;
    float lmax = -3.402823466e38f;

    if (w < n) {
        int beg = g_off[w];
        int end = beg + g_cnt[w];
        float4 d4 = __ldg((const float4*)h + (size_t)w * 32 + lane);   // dst row, once
        int j = beg;
        for (; j + 1 < end; j += 2) {
            int s0 = __ldg(g_srcs + j);
            int s1 = __ldg(g_srcs + j + 1);
            int e0 = __ldg(g_eidx + j);
            int e1 = __ldg(g_eidx + j + 1);
            float4 a0 = __ldg((const float4*)h + (size_t)s0 * 32 + lane);
            float4 a1 = __ldg((const float4*)h + (size_t)s1 * 32 + lane);
            float p0 = a0.x * d4.x + a0.y * d4.y + a0.z * d4.z + a0.w * d4.w;
            float p1 = a1.x * d4.x + a1.y * d4.y + a1.z * d4.z + a1.w * d4.w;
#pragma unroll
            for (int o = 16; o; o >>= 1) {
                p0 += __shfl_xor_sync(0xffffffffu, p0, o);
                p1 += __shfl_xor_sync(0xffffffffu, p1, o);
            }
            if (lane == 0) {
                out[e0] = p0;
                out[e1] = p1;
                lmin = fminf(lmin, fminf(p0, p1));
                lmax = fmaxf(lmax, fmaxf(p0, p1));
            }
        }
        if (j < end) {
            int s0 = __ldg(g_srcs + j);
            int e0 = __ldg(g_eidx + j);
            float4 a0 = __ldg((const float4*)h + (size_t)s0 * 32 + lane);
            float p0 = a0.x * d4.x + a0.y * d4.y + a0.z * d4.z + a0.w * d4.w;
#pragma unroll
            for (int o = 16; o; o >>= 1) p0 += __shfl_xor_sync(0xffffffffu, p0, o);
            if (lane == 0) {
                out[e0] = p0;
                lmin = fminf(lmin, p0);
                lmax = fmaxf(lmax, p0);
            }
        }
    }

#pragma unroll
    for (int o = 16; o; o >>= 1) {
        lmin = fminf(lmin, __shfl_xor_sync(0xffffffffu, lmin, o));
        lmax = fmaxf(lmax, __shfl_xor_sync(0xffffffffu, lmax, o));
    }
    __shared__ float smin[8], smax[8];
    int wd = threadIdx.x >> 5;
    if (lane == 0) { smin[wd] = lmin; smax[wd] = lmax; }
    __syncthreads();
    if (threadIdx.x == 0) {
        float m0 = smin[0], m1 = smax[0];
#pragma unroll
        for (int i = 1; i < 8; i++) { m0 = fminf(m0, smin[i]); m1 = fmaxf(m1, smax[i]); }
        atomicMin(&g_mm[0], fenc(m0));
        atomicMax(&g_mm[1], fenc(m1));
    }
}

__global__ void k_norm(float* __restrict__ out, int e) {
    int i = blockIdx.x * blockDim.x + threadIdx.x;
    if (i >= e) return;
    float mn = fdec(g_mm[0]);
    float mx = fdec(g_mm[1]);
    float inv = 1.0f / (mx - mn);
    out[i] = (out[i] - mn) * inv;
}

// ---------------- launch ------------------------------------------------------
extern "C" void kernel_launch(void* const* d_in, const int* in_sizes, int n_in,
                              void* d_out, int out_size) {
    const float* x   = (const float*)d_in[0];
    const int*   src = (const int*)d_in[1];
    const int*   dst = (const int*)d_in[2];
    const float* Ws1 = (const float*)d_in[3];
    const float* Wn1 = (const float*)d_in[4];
    const float* b1  = (const float*)d_in[5];
    const float* Ws2 = (const float*)d_in[6];
    const float* Wn2 = (const float*)d_in[7];
    const float* b2  = (const float*)d_in[8];
    float* out = (float*)d_out;

    int n = in_sizes[0] / F;
    int e = in_sizes[1];
    int nb = (n + 127) >> 7;

    void *p_cnt, *p_mm, *p_tot, *p_h1, *p_h2, *p_agg;
    void *p_Xhi, *p_Xlo, *p_AGhi, *p_AGlo, *p_H1hi, *p_H1lo, *p_W;
    cudaGetSymbolAddress(&p_cnt, g_cnt);
    cudaGetSymbolAddress(&p_mm, g_mm);
    cudaGetSymbolAddress(&p_tot, g_total);
    cudaGetSymbolAddress(&p_h1, g_h1);
    cudaGetSymbolAddress(&p_h2, g_h2);
    cudaGetSymbolAddress(&p_agg, g_agg);
    cudaGetSymbolAddress(&p_Xhi, g_Xhi);
    cudaGetSymbolAddress(&p_Xlo, g_Xlo);
    cudaGetSymbolAddress(&p_AGhi, g_AGhi);
    cudaGetSymbolAddress(&p_AGlo, g_AGlo);
    cudaGetSymbolAddress(&p_H1hi, g_H1hi);
    cudaGetSymbolAddress(&p_H1lo, g_H1lo);
    cudaGetSymbolAddress(&p_W, g_Wimg);

    const int tpb = 256;
    const int SMEM = 1024 + 131072 + 65536;   // 197,632 B
    cudaFuncSetAttribute(k_mma, cudaFuncAttributeMaxDynamicSharedMemorySize, SMEM);

    cudaMemsetAsync(p_cnt, 0, (size_t)n * sizeof(int), 0);
    cudaMemsetAsync(p_tot, 0, 4, 0);
    cudaMemsetAsync(p_mm, 0xFF, 4, 0);
    cudaMemsetAsync((char*)p_mm + 4, 0x00, 4, 0);

    // CSR build (by dst)
    k_count<<<(e + tpb - 1) / tpb, tpb>>>(dst, e);
    k_offsets<<<(n + tpb - 1) / tpb, tpb>>>(n);
    k_fill<<<(e + tpb - 1) / tpb, tpb>>>(src, dst, e);

    // conversions
    k_conv<<<(nb * 2048 + tpb - 1) / tpb, tpb>>>(x, (uint8_t*)p_Xhi, (uint8_t*)p_Xlo, n, nb);
    k_convw<<<(16384 + tpb - 1) / tpb, tpb>>>(Ws1, Wn1, Ws2, Wn2);

    int gatherBlocks = ((n * 32) + tpb - 1) / tpb;

    // layer 1
    k_gather<<<gatherBlocks, tpb>>>(x, n);
    k_conv<<<(nb * 2048 + tpb - 1) / tpb, tpb>>>((const float*)p_agg,
                                                 (uint8_t*)p_AGhi, (uint8_t*)p_AGlo, n, nb);
    k_mma<<<nb, 256, SMEM>>>((const uint8_t*)p_Xhi, (const uint8_t*)p_Xlo,
                             (const uint8_t*)p_AGhi, (const uint8_t*)p_AGlo,
                             (const uint8_t*)p_W, b1, (float*)p_h1,
                             (uint8_t*)p_H1hi, (uint8_t*)p_H1lo, n);

    // layer 2
    k_gather<<<gatherBlocks, tpb>>>((const float*)p_h1, n);
    k_conv<<<(nb * 2048 + tpb - 1) / tpb, tpb>>>((const float*)p_agg,
                                                 (uint8_t*)p_AGhi, (uint8_t*)p_AGlo, n, nb);
    k_mma<<<nb, 256, SMEM>>>((const uint8_t*)p_H1hi, (const uint8_t*)p_H1lo,
                             (const uint8_t*)p_AGhi, (const uint8_t*)p_AGlo,
                             (const uint8_t*)((char*)p_W + 131072), b2, (float*)p_h2,
                             (uint8_t*)0, (uint8_t*)0, n);

    // CSR edge scores + min/max + normalize
    k_score<<<gatherBlocks, tpb>>>((const float*)p_h2, out, n);
    k_norm<<<(e + tpb - 1) / tpb, tpb>>>(out, e);
}

// round 8
// speedup vs baseline: 3.0209x; 1.0951x over previous
#include <cuda_runtime.h>
#include <cuda_bf16.h>
#include <math.h>
#include <stdint.h>

#define NMAX 100000
#define EMAX 1600000
#define F 128
#define NB_MAX 782                       // ceil(100000/128)
#define AIMG 32768                       // one 128x128 bf16 fragment image

// ---------------- scratch (device globals) ----------------------------------
__device__ int   g_cnt[NMAX];
__device__ int   g_off[NMAX];
__device__ int   g_pos[NMAX];
__device__ int   g_total;
__device__ int   g_srcs[EMAX];
__device__ int   g_eidx[EMAX];
__device__ float g_deg[NMAX];
__device__ float g_agg[(size_t)NMAX * F];
__device__ float g_h1[(size_t)NMAX * F];
__device__ float g_h2[(size_t)NMAX * F];
__device__ unsigned int g_mm[2];

// layer-1 output as next-layer A fragment images
__device__ uint8_t g_H1hi[(size_t)NB_MAX * AIMG];
__device__ uint8_t g_H1lo[(size_t)NB_MAX * AIMG];
// W images: [layer][ self(hi,lo), neigh(hi,lo) ], contiguous 128KB per layer
__device__ uint8_t g_Wimg[2 * 4 * 32768];

// ---------------- helpers -----------------------------------------------------
__device__ __forceinline__ unsigned fenc(float f) {
    unsigned u = __float_as_uint(f);
    return (u & 0x80000000u) ? ~u : (u | 0x80000000u);
}
__device__ __forceinline__ float fdec(unsigned u) {
    return __uint_as_float((u & 0x80000000u) ? (u ^ 0x80000000u) : ~u);
}
__device__ __forceinline__ uint32_t pkf(float a, float b) {
    __nv_bfloat162 t = __floats2bfloat162_rn(a, b);
    return *(uint32_t*)&t;
}
__device__ __forceinline__ void split2(float a, float b, uint32_t& hi, uint32_t& lo) {
    __nv_bfloat16 ha = __float2bfloat16(a), hb = __float2bfloat16(b);
    __nv_bfloat162 h2 = __halves2bfloat162(ha, hb);
    hi = *(uint32_t*)&h2;
    lo = pkf(a - __bfloat162float(ha), b - __bfloat162float(hb));
}
__device__ __forceinline__ uint32_t smem_u32(const void* p) {
    uint32_t a;
    asm("{ .reg .u64 t; cvta.to.shared.u64 t, %1; cvt.u32.u64 %0, t; }" : "=r"(a) : "l"(p));
    return a;
}
__device__ __forceinline__ void mb_init(uint32_t m, uint32_t c) {
    asm volatile("mbarrier.init.shared.b64 [%0], %1;" :: "r"(m), "r"(c) : "memory");
}
__device__ __forceinline__ void mb_extx(uint32_t m, uint32_t bytes) {
    asm volatile("mbarrier.arrive.expect_tx.shared.b64 _, [%0], %1;" :: "r"(m), "r"(bytes) : "memory");
}
__device__ __forceinline__ void mb_wait(uint32_t m, uint32_t parity) {
    asm volatile(
        "{\n\t.reg .pred P;\n\t"
        "WL_%=: mbarrier.try_wait.parity.shared::cta.b64 P, [%0], %1;\n\t"
        "@P bra WD_%=;\n\t bra WL_%=;\n\tWD_%=:\n\t}"
        :: "r"(m), "r"(parity) : "memory");
}
__device__ __forceinline__ void bulk_g2s(uint32_t dst, const void* src, uint32_t bytes, uint32_t mbar) {
    asm volatile("cp.async.bulk.shared::cta.global.mbarrier::complete_tx::bytes [%0], [%1], %2, [%3];"
                 :: "r"(dst), "l"(src), "r"(bytes), "r"(mbar) : "memory");
}
__device__ __forceinline__ void mma_bf16(float* d, const uint4 a, const uint2 b) {
    asm volatile(
        "mma.sync.aligned.m16n8k16.row.col.f32.bf16.bf16.f32 "
        "{%0,%1,%2,%3}, {%4,%5,%6,%7}, {%8,%9}, {%0,%1,%2,%3};"
        : "+f"(d[0]), "+f"(d[1]), "+f"(d[2]), "+f"(d[3])
        : "r"(a.x), "r"(a.y), "r"(a.z), "r"(a.w), "r"(b.x), "r"(b.y));
}

// ---------------- CSR build --------------------------------------------------
__global__ void k_count(const int* __restrict__ dst, int e) {
    int i = blockIdx.x * blockDim.x + threadIdx.x;
    if (i < e) atomicAdd(&g_cnt[dst[i]], 1);
}

__global__ void k_offsets(int n) {
    __shared__ int wsum[8];
    __shared__ int sbase;
    int i = blockIdx.x * blockDim.x + threadIdx.x;
    int lane = threadIdx.x & 31, wid = threadIdx.x >> 5;
    int c = (i < n) ? g_cnt[i] : 0;
    int v = c;
#pragma unroll
    for (int o = 1; o < 32; o <<= 1) {
        int t = __shfl_up_sync(0xffffffffu, v, o);
        if (lane >= o) v += t;
    }
    if (lane == 31) wsum[wid] = v;
    __syncthreads();
    if (wid == 0) {
        int s = (lane < 8) ? wsum[lane] : 0;
#pragma unroll
        for (int o = 1; o < 8; o <<= 1) {
            int t = __shfl_up_sync(0xffffffffu, s, o);
            if (lane >= o) s += t;
        }
        if (lane < 8) wsum[lane] = s;
        if (lane == 7) sbase = atomicAdd(&g_total, s);
    }
    __syncthreads();
    if (i < n) {
        int excl = sbase + v - c + (wid ? wsum[wid - 1] : 0);
        g_off[i] = excl;
        g_pos[i] = excl;
        g_deg[i] = 1.0f / fmaxf((float)c, 1.0f);
    }
}

__global__ void k_fill(const int* __restrict__ src, const int* __restrict__ dst, int e) {
    int i = blockIdx.x * blockDim.x + threadIdx.x;
    if (i < e) {
        int p = atomicAdd(&g_pos[dst[i]], 1);
        g_srcs[p] = src[i];
        g_eidx[p] = i;
    }
}

// W[k][n] fp32 -> B-fragment images (once, tiny)
__global__ void k_convw(const float* __restrict__ Ws1, const float* __restrict__ Wn1,
                        const float* __restrict__ Ws2, const float* __restrict__ Wn2) {
    int idx = blockIdx.x * blockDim.x + threadIdx.x;
    if (idx >= 4 * 8 * 16 * 32) return;
    int lane = idx & 31;
    int tn = (idx >> 5) & 15;
    int tk = (idx >> 9) & 7;
    int m = idx >> 12;
    const float* W = (m == 0) ? Ws1 : (m == 1) ? Wn1 : (m == 2) ? Ws2 : Wn2;
    int g = lane >> 2, t = lane & 3;
    int nn = tn * 8 + g;
    int k0 = tk * 16 + 2 * t;
    float w00 = __ldg(W + k0 * F + nn);
    float w01 = __ldg(W + (k0 + 1) * F + nn);
    float w10 = __ldg(W + (k0 + 8) * F + nn);
    float w11 = __ldg(W + (k0 + 9) * F + nn);
    uint2 hi, lo;
    split2(w00, w01, hi.x, lo.x);
    split2(w10, w11, hi.y, lo.y);
    int layer = m >> 1, which = m & 1;
    size_t base = (size_t)layer * 131072 + (size_t)which * 65536;
    size_t off = tk * 4096 + tn * 256 + lane * 8;
    *(uint2*)(g_Wimg + base + off) = hi;
    *(uint2*)(g_Wimg + base + 32768 + off) = lo;
}

// ---------------- gather: warp per node -> coalesced row-major mean ----------
__global__ void k_gather(const float* __restrict__ h, int n) {
    int w = (blockIdx.x * blockDim.x + threadIdx.x) >> 5;
    if (w >= n) return;
    int lane = threadIdx.x & 31;
    int beg = g_off[w];
    int end = beg + g_cnt[w];
    float4 acc = make_float4(0.f, 0.f, 0.f, 0.f);
    int j = beg;
    for (; j + 1 < end; j += 2) {
        int s0 = __ldg(g_srcs + j);
        int s1 = __ldg(g_srcs + j + 1);
        float4 v0 = __ldg((const float4*)h + (size_t)s0 * 32 + lane);
        float4 v1 = __ldg((const float4*)h + (size_t)s1 * 32 + lane);
        acc.x += v0.x + v1.x; acc.y += v0.y + v1.y;
        acc.z += v0.z + v1.z; acc.w += v0.w + v1.w;
    }
    if (j < end) {
        int s0 = __ldg(g_srcs + j);
        float4 v0 = __ldg((const float4*)h + (size_t)s0 * 32 + lane);
        acc.x += v0.x; acc.y += v0.y; acc.z += v0.z; acc.w += v0.w;
    }
    float inv = g_deg[w];
    acc.x *= inv; acc.y *= inv; acc.z *= inv; acc.w *= inv;
    ((float4*)g_agg)[(size_t)w * 32 + lane] = acc;
}

// ---------------- in-kernel tile conversion: fp32 row-major -> SMEM frags ----
__device__ __forceinline__ void conv_tile(const float* __restrict__ src, int n,
                                          int base_row, uint8_t* As, int tid) {
#pragma unroll
    for (int u = 0; u < 8; u++) {
        int idx = tid + u * 256;              // 0..2047
        int lane = idx & 31;
        int tk = (idx >> 5) & 7;
        int tm = idx >> 8;
        int g = lane >> 2, t = lane & 3;
        int row0 = base_row + tm * 16 + g;
        int row1 = row0 + 8;
        int k0 = tk * 16 + 2 * t;
        float2 a00 = make_float2(0.f, 0.f), a01 = a00, a10 = a00, a11 = a00;
        if (row0 < n) {
            a00 = __ldg((const float2*)(src + (size_t)row0 * F + k0));
            a01 = __ldg((const float2*)(src + (size_t)row0 * F + k0 + 8));
        }
        if (row1 < n) {
            a10 = __ldg((const float2*)(src + (size_t)row1 * F + k0));
            a11 = __ldg((const float2*)(src + (size_t)row1 * F + k0 + 8));
        }
        uint4 hi, lo;
        split2(a00.x, a00.y, hi.x, lo.x);
        split2(a10.x, a10.y, hi.y, lo.y);
        split2(a01.x, a01.y, hi.z, lo.z);
        split2(a11.x, a11.y, hi.w, lo.w);
        uint32_t off = tm * 4096 + tk * 512 + lane * 16;
        *(uint4*)(As + off) = hi;
        *(uint4*)(As + 32768 + off) = lo;
    }
}

// ---------------- mma.sync GEMM, conversions fused ---------------------------
// out[128b..][128] = Aself@Wself + Aneigh@Wneigh + bias, bf16 3-term split.
// Self: fragment images via bulk (selfHi != 0) or in-kernel conversion of selfF.
// Neigh: always in-kernel conversion of neighF (between phases).
// SMEM: [ctrl 1KB][W 128KB][A 64KB] = 193.5KB, 1 block/SM.
__global__ void __launch_bounds__(256, 1)
k_mma(const float* __restrict__ selfF,
      const uint8_t* __restrict__ selfHi, const uint8_t* __restrict__ selfLo,
      const float* __restrict__ neighF,
      const uint8_t* __restrict__ Wbase, const float* __restrict__ bias,
      float* __restrict__ hout, uint8_t* __restrict__ Hhi, uint8_t* __restrict__ Hlo,
      int n) {
    extern __shared__ __align__(128) uint8_t sm[];
    const uint32_t WOFF = 1024, AOFF = 1024 + 131072;
    const int tid = threadIdx.x;
    const int lane = tid & 31, wid = tid >> 5;
    const int warp_m = wid >> 2, warp_n = wid & 3;
    const size_t b = blockIdx.x;
    uint32_t sb = smem_u32(sm);

    if (tid == 0) {
        mb_init(sb + 0, 1);
        asm volatile("fence.proxy.async.shared::cta;" ::: "memory");
    }
    __syncthreads();

    if (tid == 0) {
        if (selfHi) {
            mb_extx(sb + 0, 131072 + 65536);
            bulk_g2s(sb + WOFF, Wbase, 131072, sb + 0);
            bulk_g2s(sb + AOFF, selfHi + b * AIMG, 32768, sb + 0);
            bulk_g2s(sb + AOFF + 32768, selfLo + b * AIMG, 32768, sb + 0);
        } else {
            mb_extx(sb + 0, 131072);
            bulk_g2s(sb + WOFF, Wbase, 131072, sb + 0);
        }
    }
    // convert self tile while W streams in
    if (!selfHi) conv_tile(selfF, n, (int)b * 128, sm + AOFF, tid);
    __syncthreads();
    mb_wait(sb + 0, 0);

    float acc[4][4][4];
#pragma unroll
    for (int i = 0; i < 4; i++)
#pragma unroll
        for (int j = 0; j < 4; j++)
#pragma unroll
            for (int c = 0; c < 4; c++) acc[i][j][c] = 0.f;

#pragma unroll
    for (int phase = 0; phase < 2; phase++) {
        const uint8_t* Whi = sm + WOFF + phase * 65536;
        const uint8_t* Wlo = Whi + 32768;
        const uint8_t* Ahi = sm + AOFF;
        const uint8_t* Alo = Ahi + 32768;

        // terms sharing A-hi: hi*Whi + hi*Wlo
#pragma unroll
        for (int tk = 0; tk < 8; tk++) {
            uint4 af[4];
#pragma unroll
            for (int i = 0; i < 4; i++)
                af[i] = *(const uint4*)(Ahi + (warp_m * 4 + i) * 4096 + tk * 512 + lane * 16);
#pragma unroll
            for (int ws = 0; ws < 2; ws++) {
                const uint8_t* Ws = ws ? Wlo : Whi;
                uint2 bf[4];
#pragma unroll
                for (int j = 0; j < 4; j++)
                    bf[j] = *(const uint2*)(Ws + tk * 4096 + (warp_n * 4 + j) * 256 + lane * 8);
#pragma unroll
                for (int i = 0; i < 4; i++)
#pragma unroll
                    for (int j = 0; j < 4; j++)
                        mma_bf16(acc[i][j], af[i], bf[j]);
            }
        }
        // lo*Whi term
#pragma unroll
        for (int tk = 0; tk < 8; tk++) {
            uint4 af[4];
            uint2 bf[4];
#pragma unroll
            for (int i = 0; i < 4; i++)
                af[i] = *(const uint4*)(Alo + (warp_m * 4 + i) * 4096 + tk * 512 + lane * 16);
#pragma unroll
            for (int j = 0; j < 4; j++)
                bf[j] = *(const uint2*)(Whi + tk * 4096 + (warp_n * 4 + j) * 256 + lane * 8);
#pragma unroll
            for (int i = 0; i < 4; i++)
#pragma unroll
                for (int j = 0; j < 4; j++)
                    mma_bf16(acc[i][j], af[i], bf[j]);
        }

        if (phase == 0) {
            __syncthreads();                 // phase-0 MMAs done reading A buffer
            conv_tile(neighF, n, (int)b * 128, sm + AOFF, tid);
            __syncthreads();
        }
    }

    // epilogue: bias, fp32 out, optional next-layer fragment image
    const int g = lane >> 2, t = lane & 3;
#pragma unroll
    for (int i = 0; i < 4; i++) {
        int tm = warp_m * 4 + i;
        int row0 = (int)b * 128 + tm * 16 + g;
        int row1 = row0 + 8;
        bool l0 = row0 < n, l1 = row1 < n;
#pragma unroll
        for (int j = 0; j < 4; j++) {
            int nb8 = (warp_n * 4 + j) * 8 + 2 * t;
            float2 bv = __ldg((const float2*)(bias + nb8));
            float c0 = l0 ? acc[i][j][0] + bv.x : 0.f;
            float c1 = l0 ? acc[i][j][1] + bv.y : 0.f;
            float c2 = l1 ? acc[i][j][2] + bv.x : 0.f;
            float c3 = l1 ? acc[i][j][3] + bv.y : 0.f;
            if (l0) *(float2*)(hout + (size_t)row0 * F + nb8) = make_float2(c0, c1);
            if (l1) *(float2*)(hout + (size_t)row1 * F + nb8) = make_float2(c2, c3);
            acc[i][j][0] = c0; acc[i][j][1] = c1; acc[i][j][2] = c2; acc[i][j][3] = c3;
        }
        if (Hhi) {
#pragma unroll
            for (int jj = 0; jj < 2; jj++) {
                int tkp = warp_n * 2 + jj;
                uint4 hi, lo;
                split2(acc[i][2 * jj][0], acc[i][2 * jj][1], hi.x, lo.x);
                split2(acc[i][2 * jj][2], acc[i][2 * jj][3], hi.y, lo.y);
                split2(acc[i][2 * jj + 1][0], acc[i][2 * jj + 1][1], hi.z, lo.z);
                split2(acc[i][2 * jj + 1][2], acc[i][2 * jj + 1][3], hi.w, lo.w);
                size_t off = b * AIMG + tm * 4096 + tkp * 512 + lane * 16;
                *(uint4*)(Hhi + off) = hi;
                *(uint4*)(Hlo + off) = lo;
            }
        }
    }
}

// ---------------- CSR edge scores: warp per node, dst row register-resident --
__global__ void k_score(const float* __restrict__ h, float* __restrict__ out, int n) {
    int w = (blockIdx.x * blockDim.x + threadIdx.x) >> 5;
    int lane = threadIdx.x & 31;
    float lmin = 3.402823466e38f;
    float lmax = -3.402823466e38f;

    if (w < n) {
        int beg = g_off[w];
        int end = beg + g_cnt[w];
        float4 d4 = __ldg((const float4*)h + (size_t)w * 32 + lane);
        int j = beg;
        for (; j + 1 < end; j += 2) {
            int s0 = __ldg(g_srcs + j);
            int s1 = __ldg(g_srcs + j + 1);
            int e0 = __ldg(g_eidx + j);
            int e1 = __ldg(g_eidx + j + 1);
            float4 a0 = __ldg((const float4*)h + (size_t)s0 * 32 + lane);
            float4 a1 = __ldg((const float4*)h + (size_t)s1 * 32 + lane);
            float p0 = a0.x * d4.x + a0.y * d4.y + a0.z * d4.z + a0.w * d4.w;
            float p1 = a1.x * d4.x + a1.y * d4.y + a1.z * d4.z + a1.w * d4.w;
#pragma unroll
            for (int o = 16; o; o >>= 1) {
                p0 += __shfl_xor_sync(0xffffffffu, p0, o);
                p1 += __shfl_xor_sync(0xffffffffu, p1, o);
            }
            if (lane == 0) {
                out[e0] = p0;
                out[e1] = p1;
                lmin = fminf(lmin, fminf(p0, p1));
                lmax = fmaxf(lmax, fmaxf(p0, p1));
            }
        }
        if (j < end) {
            int s0 = __ldg(g_srcs + j);
            int e0 = __ldg(g_eidx + j);
            float4 a0 = __ldg((const float4*)h + (size_t)s0 * 32 + lane);
            float p0 = a0.x * d4.x + a0.y * d4.y + a0.z * d4.z + a0.w * d4.w;
#pragma unroll
            for (int o = 16; o; o >>= 1) p0 += __shfl_xor_sync(0xffffffffu, p0, o);
            if (lane == 0) {
                out[e0] = p0;
                lmin = fminf(lmin, p0);
                lmax = fmaxf(lmax, p0);
            }
        }
    }

#pragma unroll
    for (int o = 16; o; o >>= 1) {
        lmin = fminf(lmin, __shfl_xor_sync(0xffffffffu, lmin, o));
        lmax = fmaxf(lmax, __shfl_xor_sync(0xffffffffu, lmax, o));
    }
    __shared__ float smin[8], smax[8];
    int wd = threadIdx.x >> 5;
    if (lane == 0) { smin[wd] = lmin; smax[wd] = lmax; }
    __syncthreads();
    if (threadIdx.x == 0) {
        float m0 = smin[0], m1 = smax[0];
#pragma unroll
        for (int i = 1; i < 8; i++) { m0 = fminf(m0, smin[i]); m1 = fmaxf(m1, smax[i]); }
        atomicMin(&g_mm[0], fenc(m0));
        atomicMax(&g_mm[1], fenc(m1));
    }
}

__global__ void k_norm(float4* __restrict__ out, int e4) {
    int i = blockIdx.x * blockDim.x + threadIdx.x;
    if (i >= e4) return;
    float mn = fdec(g_mm[0]);
    float inv = 1.0f / (fdec(g_mm[1]) - mn);
    float4 v = out[i];
    v.x = (v.x - mn) * inv; v.y = (v.y - mn) * inv;
    v.z = (v.z - mn) * inv; v.w = (v.w - mn) * inv;
    out[i] = v;
}

__global__ void k_norm1(float* __restrict__ out, int b, int e) {
    int i = b + blockIdx.x * blockDim.x + threadIdx.x;
    if (i >= e) return;
    float mn = fdec(g_mm[0]);
    float inv = 1.0f / (fdec(g_mm[1]) - mn);
    out[i] = (out[i] - mn) * inv;
}

// ---------------- launch ------------------------------------------------------
extern "C" void kernel_launch(void* const* d_in, const int* in_sizes, int n_in,
                              void* d_out, int out_size) {
    const float* x   = (const float*)d_in[0];
    const int*   src = (const int*)d_in[1];
    const int*   dst = (const int*)d_in[2];
    const float* Ws1 = (const float*)d_in[3];
    const float* Wn1 = (const float*)d_in[4];
    const float* b1  = (const float*)d_in[5];
    const float* Ws2 = (const float*)d_in[6];
    const float* Wn2 = (const float*)d_in[7];
    const float* b2  = (const float*)d_in[8];
    float* out = (float*)d_out;

    int n = in_sizes[0] / F;
    int e = in_sizes[1];
    int nb = (n + 127) >> 7;

    void *p_cnt, *p_mm, *p_tot, *p_h1, *p_h2, *p_agg;
    void *p_H1hi, *p_H1lo, *p_W;
    cudaGetSymbolAddress(&p_cnt, g_cnt);
    cudaGetSymbolAddress(&p_mm, g_mm);
    cudaGetSymbolAddress(&p_tot, g_total);
    cudaGetSymbolAddress(&p_h1, g_h1);
    cudaGetSymbolAddress(&p_h2, g_h2);
    cudaGetSymbolAddress(&p_agg, g_agg);
    cudaGetSymbolAddress(&p_H1hi, g_H1hi);
    cudaGetSymbolAddress(&p_H1lo, g_H1lo);
    cudaGetSymbolAddress(&p_W, g_Wimg);

    const int tpb = 256;
    const int SMEM = 1024 + 131072 + 65536;   // 197,632 B
    cudaFuncSetAttribute(k_mma, cudaFuncAttributeMaxDynamicSharedMemorySize, SMEM);

    cudaMemsetAsync(p_cnt, 0, (size_t)n * sizeof(int), 0);
    cudaMemsetAsync(p_tot, 0, 4, 0);
    cudaMemsetAsync(p_mm, 0xFF, 4, 0);
    cudaMemsetAsync((char*)p_mm + 4, 0x00, 4, 0);

    // CSR build (by dst)
    k_count<<<(e + tpb - 1) / tpb, tpb>>>(dst, e);
    k_offsets<<<(n + tpb - 1) / tpb, tpb>>>(n);
    k_fill<<<(e + tpb - 1) / tpb, tpb>>>(src, dst, e);

    // W conversion (tiny, once)
    k_convw<<<(16384 + tpb - 1) / tpb, tpb>>>(Ws1, Wn1, Ws2, Wn2);

    int gatherBlocks = ((n * 32) + tpb - 1) / tpb;

    // layer 1: self = x (in-kernel conv), neigh = agg (in-kernel conv)
    k_gather<<<gatherBlocks, tpb>>>(x, n);
    k_mma<<<nb, 256, SMEM>>>(x, (const uint8_t*)0, (const uint8_t*)0,
                             (const float*)p_agg,
                             (const uint8_t*)p_W, b1, (float*)p_h1,
                             (uint8_t*)p_H1hi, (uint8_t*)p_H1lo, n);

    // layer 2: self = H1 fragment images (bulk), neigh = agg (in-kernel conv)
    k_gather<<<gatherBlocks, tpb>>>((const float*)p_h1, n);
    k_mma<<<nb, 256, SMEM>>>((const float*)0, (const uint8_t*)p_H1hi, (const uint8_t*)p_H1lo,
                             (const float*)p_agg,
                             (const uint8_t*)((char*)p_W + 131072), b2, (float*)p_h2,
                             (uint8_t*)0, (uint8_t*)0, n);

    // CSR edge scores + min/max + normalize
    k_score<<<gatherBlocks, tpb>>>((const float*)p_h2, out, n);
    int e4 = e >> 2;
    if (e4 > 0) k_norm<<<(e4 + tpb - 1) / tpb, tpb>>>((float4*)out, e4);
    if (e & 3) k_norm1<<<1, 256>>>(out, e4 * 4, e);
}